// round 11
// baseline (speedup 1.0000x reference)
#include <cuda_runtime.h>
#include <cuda_bf16.h>
#include <math.h>
#include <stdint.h>

// ---------------- problem constants ----------------
#define Bsz   131072
#define Dd    256
#define Lc    8
#define NCc   10
#define BN_EPS 1e-5f
#define DGCONST -235.24826450039622f   // D * GCONST

#define MROW  64
#define NTHR  256
#define NBLK  (Bsz/MROW)      // 2048 CTAs

// smem byte offsets (all swizzled images, no padding)
#define XHIo 0
#define XLOo 32768
#define HBo  65536
#define BWo  98304            // 2 x 65536
#define SMEMSZ 229376

// ---------------- static device scratch ----------------
__device__ float g_bufA[(size_t)Bsz*Dd];          // h
__device__ float g_scale[Lc*Dd];
__device__ float g_sumlog[Lc];
__device__ float g_po[Lc*Dd];
__device__ float g_part[(size_t)NBLK*2*Dd];
__device__ float g_stats[2*Dd];
// pre-swizzled bf16 weight images (chunked K=64 smem layout)
__device__ __nv_bfloat16 g_w1t[(size_t)Lc*32768];
__device__ __nv_bfloat16 g_w2t[(size_t)Lc*65536];   // column-PERMUTED (see prep)
__device__ __nv_bfloat16 g_ph [(size_t)Lc*65536];   // P' = P*diag(scale), hi
__device__ __nv_bfloat16 g_pl [(size_t)Lc*65536];
__device__ __nv_bfloat16 g_whh[65536];
__device__ __nv_bfloat16 g_whl[65536];

// ---------------- helpers ----------------
__device__ __forceinline__ uint32_t packbf2(float a, float b) {
    __nv_bfloat162 t = __floats2bfloat162_rn(a, b);
    return *(uint32_t*)&t;
}
__device__ __forceinline__ float2 unpackbf2(uint32_t w) {
    __nv_bfloat162 t = *(__nv_bfloat162*)&w;
    return __bfloat1622float2(t);
}
__device__ __forceinline__ void split2(float a, float b, uint32_t& hw, uint32_t& lw) {
    __nv_bfloat16 ha = __float2bfloat16(a), hb = __float2bfloat16(b);
    float la = a - __bfloat162float(ha), lb = b - __bfloat162float(hb);
    __nv_bfloat162 h; h.x = ha; h.y = hb;
    hw = *(uint32_t*)&h;
    lw = packbf2(la, lb);
}
__device__ __forceinline__ float fast_tanh_scaled(float a) {
    float e = __expf(-0.2f * a);
    return 1.9f * __fdividef(1.f - e, 1.f + e);
}
__device__ __forceinline__ void cpab(void* dst_smem, const void* src) {
    unsigned s = (unsigned)__cvta_generic_to_shared(dst_smem);
    asm volatile("cp.async.cg.shared.global [%0], [%1], 16;" :: "r"(s), "l"(src));
}
#define CP_COMMIT asm volatile("cp.async.commit_group;")
#define CP_WAIT0  asm volatile("cp.async.wait_group 0;")

#define MMA(cd, a0, a1, a2, a3, b0, b1) \
    asm volatile("mma.sync.aligned.m16n8k16.row.col.f32.bf16.bf16.f32 " \
        "{%0,%1,%2,%3}, {%4,%5,%6,%7}, {%8,%9}, {%0,%1,%2,%3};" \
        : "+f"((cd)[0]), "+f"((cd)[1]), "+f"((cd)[2]), "+f"((cd)[3]) \
        : "r"(a0), "r"(a1), "r"(a2), "r"(a3), "r"(b0), "r"(b1))

#define LDSM4(r0, r1, r2, r3, addr) \
    asm volatile("ldmatrix.sync.aligned.m8n8.x4.shared.b16 {%0,%1,%2,%3}, [%4];" \
        : "=r"(r0), "=r"(r1), "=r"(r2), "=r"(r3) : "r"(addr))

__device__ __forceinline__ void stage32(char* dst, const __nv_bfloat16* src, int tid) {
    const char* s = (const char*)src;
    #pragma unroll
    for (int i = 0; i < 8; i++) cpab(dst + tid*16 + i*4096, s + tid*16 + i*4096);
}
__device__ __forceinline__ int imgoff(int n, int k) {
    return n*64 + (((k >> 3) ^ (n & 7)) << 3) + (k & 7);
}

// ---------------- preprocessing (3 launches) ----------------
__global__ void prep_scale(const float* __restrict__ gs) {
    __shared__ float red[256];
    int l = blockIdx.x, d = threadIdx.x;
    float x  = 0.5f * gs[l*Dd + d];
    float sp = (x > 20.f) ? x : log1pf(expf(x));
    float s  = 0.2f * sp;
    g_scale[l*Dd + d] = s;
    red[d] = logf(s);
    __syncthreads();
    #pragma unroll
    for (int o = 128; o; o >>= 1) { if (d < o) red[d] += red[d + o]; __syncthreads(); }
    if (d == 0) g_sumlog[l] = red[0];
}
__global__ void prep_wimg(const float* __restrict__ W1, const float* __restrict__ W2,
                          const float* __restrict__ Wh1) {
    int idx = blockIdx.x * 256 + threadIdx.x;
    if (idx < Lc*32768) {
        int k = idx & 127, n = (idx >> 7) & 255, l = idx >> 15;
        g_w1t[(size_t)l*32768 + (k>>6)*16384 + imgoff(n, k & 63)] =
            __float2bfloat16(W1[((size_t)l*128 + k)*256 + n]);
    } else if (idx < Lc*32768 + Lc*65536) {
        int j = idx - Lc*32768;
        int k = j & 255, n = (j >> 8) & 255, l = j >> 16;
        // column permutation: warp (owner = (n&127)>>5) owns cols [o*32,o*32+32) and +128
        int owner = (n & 127) >> 5, half = n >> 7, v = n & 31;
        int jr = owner*64 + half*32 + v;
        g_w2t[(size_t)l*65536 + (k>>6)*16384 + imgoff(jr, k & 63)] =
            __float2bfloat16(W2[((size_t)l*256 + k)*256 + n]);
    } else {
        int j = idx - (Lc*32768 + Lc*65536);
        int k = j & 255, n = j >> 8;
        float v = Wh1[(size_t)k*256 + n];
        __nv_bfloat16 hi = __float2bfloat16(v);
        size_t o = (size_t)(k>>6)*16384 + imgoff(n, k & 63);
        g_whh[o] = hi;
        g_whl[o] = __float2bfloat16(v - __bfloat162float(hi));
    }
}
__global__ void prep_pimg(const float* __restrict__ P, const float* __restrict__ go) {
    int idx = blockIdx.x * 256 + threadIdx.x;
    if (idx < Lc*65536) {
        int k = idx & 255, n = (idx >> 8) & 255, l = idx >> 16;
        float v = P[((size_t)l*256 + n)*256 + k] * g_scale[l*Dd + k];
        __nv_bfloat16 hi = __float2bfloat16(v);
        size_t o = (size_t)l*65536 + (k>>6)*16384 + imgoff(n, k & 63);
        g_ph[o] = hi;
        g_pl[o] = __float2bfloat16(v - __bfloat162float(hi));
    } else {
        int j = idx - Lc*65536;
        int l = j >> 8, n = j & 255;
        const float* pr = P + ((size_t)l*256 + n)*256;
        const float* o  = go + l*Dd;
        float acc = 0.f;
        for (int k = 0; k < 256; k++) acc += o[k] * pr[k];
        g_po[l*Dd + n] = acc;
    }
}

// ---------------- mega-fused: flow(8 layers) + log_px + head GEMM ----------------
__global__ void __launch_bounds__(NTHR, 1) flow_fused(
    const float* __restrict__ xin, float* __restrict__ hout,
    const float* __restrict__ b1, const float* __restrict__ b2,
    const float* __restrict__ bh1, float* __restrict__ logpx)
{
    extern __shared__ char smem[];
    const uint32_t su = (uint32_t)__cvta_generic_to_shared(smem);
    const uint32_t XHI = su + XHIo, XLO = su + XLOo, HBu = su + HBo, BWu = su + BWo;
    char* bw = smem + BWo;

    const int tid = threadIdx.x, lane = tid & 31, wid = tid >> 5;
    const int warpM = wid >> 2, warpN = wid & 3;     // 2M x 4N, warp tile 32x64
    const int g = lane >> 2, t = lane & 3;
    const int mrow0 = warpM * 32;
    const int n0 = warpN * 64;
    const int laneHi = lane >> 4;
    const int key = lane & 7;
    const int aRowB = (lane & 15) * 512;
    const int nloc = ((lane >> 4) << 3) + (lane & 7);
    int bRowP[4];
    #pragma unroll
    for (int p = 0; p < 4; p++) bRowP[p] = (n0 + p*16 + nloc) * 128;
    const int bsel = (lane >> 3) & 1;

    // prologue: stage layer-0 W1 in full (64KB -> buf0 == wb(layer0))
    stage32(bw,         g_w1t,         tid);
    stage32(bw + 32768, g_w1t + 16384, tid); CP_COMMIT;

    // load + split input x once
    {
        const float4* src = (const float4*)(xin + (size_t)blockIdx.x * MROW * Dd);
        #pragma unroll
        for (int i = tid; i < MROW * Dd / 4; i += NTHR) {
            int r = i >> 6, c = (i & 63) * 4;
            float4 v = src[i];
            uint32_t h0, l0, h1, l1;
            split2(v.x, v.y, h0, l0);
            split2(v.z, v.w, h1, l1);
            int off = r*512 + (((c >> 3) ^ (r & 7)) << 4) + (c & 7)*2;
            *(uint2*)(smem + XHIo + off) = make_uint2(h0, h1);
            *(uint2*)(smem + XLOo + off) = make_uint2(l0, l1);
        }
    }

    float cacc[2][8][4];
    float ldacc = 0.f;

    #pragma unroll 1
    for (int layer = 0; layer < Lc; layer++) {
        const float* bb1 = b1 + layer*Dd;
        const float* bb2 = b2 + layer*Dd;
        const __nv_bfloat16* w2img = g_w2t + (size_t)layer*65536;
        const __nv_bfloat16* phimg = g_ph  + (size_t)layer*65536;
        const __nv_bfloat16* plimg = g_pl  + (size_t)layer*65536;
        const uint32_t wbo = (uint32_t)((layer & 1) * 65536);
        const uint32_t obo = 65536u - wbo;

        // ===== GEMM1: H = relu(x1_hi @ W1 + b1), K=128, whole W1 in wb =====
        #pragma unroll
        for (int nt = 0; nt < 8; nt++) {
            int c = n0 + (nt >> 1)*16 + (nt & 1)*8 + 2*t;
            float f0 = __ldg(bb1 + c), f1 = __ldg(bb1 + c + 1);
            #pragma unroll
            for (int mt = 0; mt < 2; mt++) {
                cacc[mt][nt][0] = f0; cacc[mt][nt][1] = f1;
                cacc[mt][nt][2] = f0; cacc[mt][nt][3] = f1;
            }
        }
        CP_WAIT0; __syncthreads();                                   // S1
        stage32(bw + obo,         w2img,         tid);
        stage32(bw + obo + 32768, w2img + 16384, tid); CP_COMMIT;
        #pragma unroll
        for (int kk = 0; kk < 8; kk++) {
            int gA = kk*2 + laneHi;
            uint32_t A[2][4], B[4][4];
            #pragma unroll
            for (int mt = 0; mt < 2; mt++)
                LDSM4(A[mt][0], A[mt][1], A[mt][2], A[mt][3],
                      XHI + (uint32_t)((mrow0 + mt*16)*512 + aRowB + ((gA ^ key) << 4)));
            uint32_t bb = BWu + wbo + (uint32_t)((kk >> 2) * 32768);
            uint32_t bsw = (uint32_t)(((((kk & 3)*2) + bsel) ^ key) << 4);
            #pragma unroll
            for (int p = 0; p < 4; p++)
                LDSM4(B[p][0], B[p][1], B[p][2], B[p][3], bb + (uint32_t)bRowP[p] + bsw);
            #pragma unroll
            for (int p = 0; p < 4; p++)
                #pragma unroll
                for (int q = 0; q < 2; q++) {
                    int nt = p*2 + q;
                    MMA(cacc[0][nt], A[0][0], A[0][1], A[0][2], A[0][3], B[p][q*2], B[p][q*2+1]);
                    MMA(cacc[1][nt], A[1][0], A[1][1], A[1][2], A[1][3], B[p][q*2], B[p][q*2+1]);
                }
        }
        // relu -> HB (unpermuted)
        #pragma unroll
        for (int nt = 0; nt < 8; nt++) {
            int c = n0 + (nt >> 1)*16 + (nt & 1)*8 + 2*t;
            int csw = ((c >> 3) ^ g) << 4;
            #pragma unroll
            for (int mt = 0; mt < 2; mt++) {
                int r = mrow0 + mt*16 + g;
                float* cf = cacc[mt][nt];
                *(uint32_t*)(smem + HBo + r*512     + csw + 4*t) =
                    packbf2(fmaxf(cf[0], 0.f), fmaxf(cf[1], 0.f));
                *(uint32_t*)(smem + HBo + (r+8)*512 + csw + 4*t) =
                    packbf2(fmaxf(cf[2], 0.f), fmaxf(cf[3], 0.f));
            }
        }

        // ===== GEMM2: A2 = H @ W2perm + b2, K=256 (output cols permuted) =====
        // acc (p,q): actual col = (p>>1)*128 + warpN*32 + (p&1)*16 + q*8 + 2t
        #pragma unroll
        for (int nt = 0; nt < 8; nt++) {
            int p = nt >> 1, q = nt & 1;
            int c2 = (p >> 1)*128 + warpN*32 + (p & 1)*16 + q*8 + 2*t;
            float f0 = __ldg(bb2 + c2), f1 = __ldg(bb2 + c2 + 1);
            #pragma unroll
            for (int mt = 0; mt < 2; mt++) {
                cacc[mt][nt][0] = f0; cacc[mt][nt][1] = f1;
                cacc[mt][nt][2] = f0; cacc[mt][nt][3] = f1;
            }
        }
        #pragma unroll 1
        for (int half2 = 0; half2 < 2; half2++) {
            CP_WAIT0; __syncthreads();                               // S2 / S3
            if (half2 == 0) {
                stage32(bw + wbo,         w2img + 32768, tid);
                stage32(bw + wbo + 32768, w2img + 49152, tid); CP_COMMIT;
            } else {
                stage32(bw + obo,         phimg, tid);
                stage32(bw + obo + 32768, plimg, tid); CP_COMMIT;
            }
            uint32_t cur = BWu + ((half2 == 0) ? obo : wbo);
            #pragma unroll
            for (int kk = 0; kk < 8; kk++) {
                int gA = half2*16 + kk*2 + laneHi;
                uint32_t A[2][4], B[4][4];
                #pragma unroll
                for (int mt = 0; mt < 2; mt++)
                    LDSM4(A[mt][0], A[mt][1], A[mt][2], A[mt][3],
                          HBu + (uint32_t)((mrow0 + mt*16)*512 + aRowB + ((gA ^ key) << 4)));
                uint32_t bb = cur + (uint32_t)((kk >> 2) * 32768);
                uint32_t bsw = (uint32_t)(((((kk & 3)*2) + bsel) ^ key) << 4);
                #pragma unroll
                for (int p = 0; p < 4; p++)
                    LDSM4(B[p][0], B[p][1], B[p][2], B[p][3], bb + (uint32_t)bRowP[p] + bsw);
                #pragma unroll
                for (int p = 0; p < 4; p++)
                    #pragma unroll
                    for (int q = 0; q < 2; q++) {
                        int nt = p*2 + q;
                        MMA(cacc[0][nt], A[0][0], A[0][1], A[0][2], A[0][3], B[p][q*2], B[p][q*2+1]);
                        MMA(cacc[1][nt], A[1][0], A[1][1], A[1][2], A[1][3], B[p][q*2], B[p][q*2+1]);
                    }
            }
        }
        CP_WAIT0; __syncthreads();                                   // S4
        stage32(bw + wbo,         phimg + 16384, tid);
        stage32(bw + wbo + 32768, plimg + 16384, tid); CP_COMMIT;

        // ===== coupling epilogue (register-local; s -> HB for logdet only) =====
        // s tiles nt_s 0..3 (p 0,1) pair with x2 tiles nt_s+4 (p 2,3)
        #pragma unroll
        for (int nts = 0; nts < 4; nts++) {
            int cs = warpN*32 + (nts >> 1)*16 + (nts & 1)*8 + 2*t;
            int cx = 128 + cs;
            #pragma unroll
            for (int mt = 0; mt < 2; mt++) {
                #pragma unroll
                for (int half = 0; half < 2; half++) {
                    int i0 = half*2, r = mrow0 + mt*16 + g + half*8;
                    float s0 = fast_tanh_scaled(cacc[mt][nts][i0]);
                    float s1 = fast_tanh_scaled(cacc[mt][nts][i0 + 1]);
                    *(uint32_t*)(smem + HBo + r*512 + (((cs >> 3) ^ g) << 4) + 4*t) =
                        packbf2(s0, s1);
                    float a20 = 0.1f * cacc[mt][nts + 4][i0];
                    float a21 = 0.1f * cacc[mt][nts + 4][i0 + 1];
                    int xo = r*512 + (((cx >> 3) ^ g) << 4) + 4*t;
                    float2 hv = unpackbf2(*(uint32_t*)(smem + XHIo + xo));
                    float2 lv = unpackbf2(*(uint32_t*)(smem + XLOo + xo));
                    float v0 = (hv.x + lv.x) * __expf(s0) + a20;
                    float v1 = (hv.y + lv.y) * __expf(s1) + a21;
                    uint32_t hw, lw; split2(v0, v1, hw, lw);
                    *(uint32_t*)(smem + XHIo + xo) = hw;
                    *(uint32_t*)(smem + XLOo + xo) = lw;
                }
            }
        }

        // ===== GEMM3: Xnew = Xc @ P'^T + po, 3-term split, K=256 =====
        {
            const float* po = g_po + layer*Dd;
            #pragma unroll
            for (int nt = 0; nt < 8; nt++) {
                int c = n0 + (nt >> 1)*16 + (nt & 1)*8 + 2*t;
                float f0 = __ldg(po + c), f1 = __ldg(po + c + 1);
                #pragma unroll
                for (int mt = 0; mt < 2; mt++) {
                    cacc[mt][nt][0] = f0; cacc[mt][nt][1] = f1;
                    cacc[mt][nt][2] = f0; cacc[mt][nt][3] = f1;
                }
            }
            #pragma unroll 1
            for (int ch = 0; ch < 4; ch++) {
                if (ch > 0) {
                    CP_WAIT0; __syncthreads();                       // S6..S8
                    if (ch < 3) {
                        uint32_t dsto = (ch == 1) ? obo : wbo;
                        stage32(bw + dsto,         phimg + (ch+1)*16384, tid);
                        stage32(bw + dsto + 32768, plimg + (ch+1)*16384, tid); CP_COMMIT;
                    } else if (layer + 1 < Lc) {
                        const __nv_bfloat16* w1n = g_w1t + (size_t)(layer+1)*32768;
                        stage32(bw + obo,         w1n,         tid);
                        stage32(bw + obo + 32768, w1n + 16384, tid); CP_COMMIT;
                    } else {
                        stage32(bw + obo,         g_whh, tid);
                        stage32(bw + obo + 32768, g_whl, tid); CP_COMMIT;
                    }
                }
                uint32_t cur = BWu + ((ch & 1) ? wbo : obo);
                #pragma unroll
                for (int ks = 0; ks < 64; ks += 16) {
                    int gA = (ch << 3) + (ks >> 3) + laneHi;
                    uint32_t Ah[2][4], Al[2][4], Bh[4][4], Bl[4][4];
                    #pragma unroll
                    for (int mt = 0; mt < 2; mt++) {
                        uint32_t abase = (uint32_t)((mrow0 + mt*16)*512 + aRowB + ((gA ^ key) << 4));
                        LDSM4(Ah[mt][0], Ah[mt][1], Ah[mt][2], Ah[mt][3], XHI + abase);
                        LDSM4(Al[mt][0], Al[mt][1], Al[mt][2], Al[mt][3], XLO + abase);
                    }
                    uint32_t bsw = (uint32_t)(((((ks >> 3) + bsel) ^ key) << 4));
                    #pragma unroll
                    for (int p = 0; p < 4; p++) {
                        LDSM4(Bh[p][0], Bh[p][1], Bh[p][2], Bh[p][3],
                              cur + (uint32_t)bRowP[p] + bsw);
                        LDSM4(Bl[p][0], Bl[p][1], Bl[p][2], Bl[p][3],
                              cur + 32768u + (uint32_t)bRowP[p] + bsw);
                    }
                    #pragma unroll
                    for (int p = 0; p < 4; p++)
                        #pragma unroll
                        for (int q = 0; q < 2; q++) {
                            int nt = p*2 + q;
                            #pragma unroll
                            for (int mt = 0; mt < 2; mt++) {
                                MMA(cacc[mt][nt], Ah[mt][0], Ah[mt][1], Ah[mt][2], Ah[mt][3], Bh[p][q*2], Bh[p][q*2+1]);
                                MMA(cacc[mt][nt], Al[mt][0], Al[mt][1], Al[mt][2], Al[mt][3], Bh[p][q*2], Bh[p][q*2+1]);
                                MMA(cacc[mt][nt], Ah[mt][0], Ah[mt][1], Ah[mt][2], Ah[mt][3], Bl[p][q*2], Bl[p][q*2+1]);
                            }
                        }
                }
            }
            __syncthreads();                                         // S9
        }

        // logdet from s image
        if (tid < MROW) {
            float rs = 0.f;
            int rk = tid & 7;
            #pragma unroll
            for (int gi = 0; gi < 16; gi++) {
                int gg = (gi + tid) & 15;
                uint4 w = *(uint4*)(smem + HBo + tid*512 + ((gg ^ rk) << 4));
                float2 p0 = unpackbf2(w.x), p1 = unpackbf2(w.y),
                       p2 = unpackbf2(w.z), p3 = unpackbf2(w.w);
                rs += (p0.x + p0.y) + (p1.x + p1.y) + (p2.x + p2.y) + (p3.x + p3.y);
            }
            ldacc += rs + g_sumlog[layer];
        }

        // split accumulators back into XHI/XLO (all layers; final = z)
        #pragma unroll
        for (int nt = 0; nt < 8; nt++) {
            int c = n0 + (nt >> 1)*16 + (nt & 1)*8 + 2*t;
            int csw = ((c >> 3) ^ g) << 4;
            #pragma unroll
            for (int mt = 0; mt < 2; mt++) {
                float* cf = cacc[mt][nt];
                #pragma unroll
                for (int half = 0; half < 2; half++) {
                    int r = mrow0 + mt*16 + g + half*8;
                    uint32_t hw, lw;
                    split2(cf[half*2 + 0], cf[half*2 + 1], hw, lw);
                    *(uint32_t*)(smem + XHIo + r*512 + csw + 4*t) = hw;
                    *(uint32_t*)(smem + XLOo + r*512 + csw + 4*t) = lw;
                }
            }
        }
    }

    // ===================== fused tail: log_px + head GEMM =====================
    {
        float* HBf = (float*)(smem + HBo);
        float z2[2][2];
        #pragma unroll
        for (int mt = 0; mt < 2; mt++)
            #pragma unroll
            for (int half = 0; half < 2; half++) {
                float s = 0.f;
                #pragma unroll
                for (int nt = 0; nt < 8; nt++) {
                    float a = cacc[mt][nt][half*2 + 0], b = cacc[mt][nt][half*2 + 1];
                    s += a*a + b*b;
                }
                s += __shfl_xor_sync(0xffffffffu, s, 1);
                s += __shfl_xor_sync(0xffffffffu, s, 2);
                z2[mt][half] = s;
            }
        CP_WAIT0;                      // head wh chunk0 arrived
        __syncthreads();               // S10
        if (t == 0) {
            #pragma unroll
            for (int mt = 0; mt < 2; mt++)
                #pragma unroll
                for (int half = 0; half < 2; half++) {
                    int r = mrow0 + mt*16 + g + half*8;
                    HBf[r*4 + warpN] = z2[mt][half];
                }
        }
        __syncthreads();               // S11
        if (tid < MROW) {
            float ss = HBf[tid*4] + HBf[tid*4+1] + HBf[tid*4+2] + HBf[tid*4+3];
            logpx[(size_t)blockIdx.x * MROW + tid] =
                (DGCONST - 0.5f*ss + ldacc) * (1.0f/Dd);
        }
    }

    // head GEMM: h = z @ Wh1 (3-term) + bh1; buffers: ob=0, wb=65536 (layer7 parity)
    {
        const uint32_t wbo = 65536u, obo = 0u;
        stage32(bw + wbo,         g_whh + 16384, tid);
        stage32(bw + wbo + 32768, g_whl + 16384, tid); CP_COMMIT;

        #pragma unroll
        for (int nt = 0; nt < 8; nt++) {
            int c = n0 + (nt >> 1)*16 + (nt & 1)*8 + 2*t;
            float f0 = __ldg(bh1 + c), f1 = __ldg(bh1 + c + 1);
            #pragma unroll
            for (int mt = 0; mt < 2; mt++) {
                cacc[mt][nt][0] = f0; cacc[mt][nt][1] = f1;
                cacc[mt][nt][2] = f0; cacc[mt][nt][3] = f1;
            }
        }
        #pragma unroll 1
        for (int ch = 0; ch < 4; ch++) {
            if (ch > 0) {
                CP_WAIT0; __syncthreads();
                if (ch < 3) {
                    uint32_t dsto = (ch == 1) ? obo : wbo;
                    stage32(bw + dsto,         g_whh + (ch+1)*16384, tid);
                    stage32(bw + dsto + 32768, g_whl + (ch+1)*16384, tid); CP_COMMIT;
                }
            }
            uint32_t cur = BWu + ((ch & 1) ? wbo : obo);
            #pragma unroll
            for (int ks = 0; ks < 64; ks += 16) {
                int gA = (ch << 3) + (ks >> 3) + laneHi;
                uint32_t Ah[2][4], Al[2][4], Bh[4][4], Bl[4][4];
                #pragma unroll
                for (int mt = 0; mt < 2; mt++) {
                    uint32_t abase = (uint32_t)((mrow0 + mt*16)*512 + aRowB + ((gA ^ key) << 4));
                    LDSM4(Ah[mt][0], Ah[mt][1], Ah[mt][2], Ah[mt][3], XHI + abase);
                    LDSM4(Al[mt][0], Al[mt][1], Al[mt][2], Al[mt][3], XLO + abase);
                }
                uint32_t bsw = (uint32_t)(((((ks >> 3) + bsel) ^ key) << 4));
                #pragma unroll
                for (int p = 0; p < 4; p++) {
                    LDSM4(Bh[p][0], Bh[p][1], Bh[p][2], Bh[p][3],
                          cur + (uint32_t)bRowP[p] + bsw);
                    LDSM4(Bl[p][0], Bl[p][1], Bl[p][2], Bl[p][3],
                          cur + 32768u + (uint32_t)bRowP[p] + bsw);
                }
                #pragma unroll
                for (int p = 0; p < 4; p++)
                    #pragma unroll
                    for (int q = 0; q < 2; q++) {
                        int nt = p*2 + q;
                        #pragma unroll
                        for (int mt = 0; mt < 2; mt++) {
                            MMA(cacc[mt][nt], Ah[mt][0], Ah[mt][1], Ah[mt][2], Ah[mt][3], Bh[p][q*2], Bh[p][q*2+1]);
                            MMA(cacc[mt][nt], Al[mt][0], Al[mt][1], Al[mt][2], Al[mt][3], Bh[p][q*2], Bh[p][q*2+1]);
                            MMA(cacc[mt][nt], Ah[mt][0], Ah[mt][1], Ah[mt][2], Ah[mt][3], Bl[p][q*2], Bl[p][q*2+1]);
                        }
                    }
            }
        }
        __syncthreads();               // S12

        // h epilogue: gmem write + fp32 overlay for BN partials
        float* stg = (float*)smem;     // [64][264]
        #pragma unroll
        for (int mt = 0; mt < 2; mt++)
            #pragma unroll
            for (int half = 0; half < 2; half++) {
                int rl = mrow0 + mt*16 + g + half*8;
                int r  = blockIdx.x * MROW + rl;
                #pragma unroll
                for (int nt = 0; nt < 8; nt++) {
                    int c = n0 + (nt >> 1)*16 + (nt & 1)*8 + 2*t;
                    float* cf = cacc[mt][nt];
                    float v0 = cf[half*2 + 0];
                    float v1 = cf[half*2 + 1];
                    *(float2*)(hout + (size_t)r*Dd + c) = make_float2(v0, v1);
                    stg[(size_t)rl*264 + c]     = v0;
                    stg[(size_t)rl*264 + c + 1] = v1;
                }
            }
        __syncthreads();               // S13
        if (tid < Dd) {
            float s = 0.f, q = 0.f;
            #pragma unroll 4
            for (int r = 0; r < MROW; r++) {
                float v = stg[(size_t)r*264 + tid];
                s += v; q += v * v;
            }
            g_part[(size_t)blockIdx.x*2*Dd + tid]      = s;
            g_part[(size_t)blockIdx.x*2*Dd + Dd + tid] = q;
        }
    }
}

// ---------------- BN stats fold ----------------
__global__ void stats_kernel(const float* __restrict__ gamma, const float* __restrict__ beta) {
    int c = threadIdx.x;
    float s0=0.f,s1=0.f,s2=0.f,s3=0.f, q0=0.f,q1=0.f,q2=0.f,q3=0.f;
    for (int i = 0; i < NBLK; i += 4) {
        s0 += g_part[(size_t)(i+0)*2*Dd + c];   q0 += g_part[(size_t)(i+0)*2*Dd + Dd + c];
        s1 += g_part[(size_t)(i+1)*2*Dd + c];   q1 += g_part[(size_t)(i+1)*2*Dd + Dd + c];
        s2 += g_part[(size_t)(i+2)*2*Dd + c];   q2 += g_part[(size_t)(i+2)*2*Dd + Dd + c];
        s3 += g_part[(size_t)(i+3)*2*Dd + c];   q3 += g_part[(size_t)(i+3)*2*Dd + Dd + c];
    }
    float s = (s0+s1)+(s2+s3), q = (q0+q1)+(q2+q3);
    float mu  = s * (1.f/Bsz);
    float var = q * (1.f/Bsz) - mu*mu;
    float a = gamma[c] * rsqrtf(var + BN_EPS);
    g_stats[c]      = a;
    g_stats[Dd + c] = beta[c] - mu * a;
}

// ---------------- logits ----------------
__global__ void __launch_bounds__(256) logits_kernel(
    const float* __restrict__ h, const float* __restrict__ Wh2,
    const float* __restrict__ bh2, float* __restrict__ out)
{
    __shared__ float w2s[Dd*NCc];
    __shared__ float As[Dd], Bs[Dd];
    int tid = threadIdx.x;
    for (int i = tid; i < Dd*NCc; i += 256) w2s[i] = Wh2[i];
    if (tid < Dd) { As[tid] = g_stats[tid]; Bs[tid] = g_stats[Dd + tid]; }
    __syncthreads();

    int warp = tid >> 5, lane = tid & 31;
    size_t row = (size_t)blockIdx.x * 8 + warp;
    const float4* hr = (const float4*)(h + row*Dd);
    float4 v0 = hr[lane*2], v1 = hr[lane*2 + 1];
    int k0 = lane * 8;
    float hn[8];
    hn[0] = fmaxf(v0.x*As[k0+0] + Bs[k0+0], 0.f);
    hn[1] = fmaxf(v0.y*As[k0+1] + Bs[k0+1], 0.f);
    hn[2] = fmaxf(v0.z*As[k0+2] + Bs[k0+2], 0.f);
    hn[3] = fmaxf(v0.w*As[k0+3] + Bs[k0+3], 0.f);
    hn[4] = fmaxf(v1.x*As[k0+4] + Bs[k0+4], 0.f);
    hn[5] = fmaxf(v1.y*As[k0+5] + Bs[k0+5], 0.f);
    hn[6] = fmaxf(v1.z*As[k0+6] + Bs[k0+6], 0.f);
    hn[7] = fmaxf(v1.w*As[k0+7] + Bs[k0+7], 0.f);

    float acc[NCc];
    #pragma unroll
    for (int c = 0; c < NCc; c++) acc[c] = 0.f;
    #pragma unroll
    for (int kk = 0; kk < 8; kk++) {
        float x = hn[kk];
        const float* wr = &w2s[(k0+kk)*NCc];
        #pragma unroll
        for (int c = 0; c < NCc; c++) acc[c] += x * wr[c];
    }
    #pragma unroll
    for (int c = 0; c < NCc; c++) {
        #pragma unroll
        for (int o = 16; o; o >>= 1) acc[c] += __shfl_down_sync(0xffffffffu, acc[c], o);
    }
    if (lane == 0) {
        #pragma unroll
        for (int c = 0; c < NCc; c++) out[row*NCc + c] = acc[c] + __ldg(bh2 + c);
    }
}

// ---------------- launch ----------------
extern "C" void kernel_launch(void* const* d_in, const int* in_sizes, int n_in,
                              void* d_out, int out_size)
{
    const float* feat  = (const float*)d_in[0];
    const float* W1    = (const float*)d_in[1];
    const float* b1    = (const float*)d_in[2];
    const float* W2    = (const float*)d_in[3];
    const float* b2    = (const float*)d_in[4];
    const float* gs    = (const float*)d_in[5];
    const float* go    = (const float*)d_in[6];
    const float* P     = (const float*)d_in[7];
    const float* Wh1   = (const float*)d_in[8];
    const float* bh1   = (const float*)d_in[9];
    const float* gamma = (const float*)d_in[10];
    const float* beta  = (const float*)d_in[11];
    const float* Wh2   = (const float*)d_in[12];
    const float* bh2   = (const float*)d_in[13];
    float* out = (float*)d_out;

    cudaFuncSetAttribute(flow_fused, cudaFuncAttributeMaxDynamicSharedMemorySize, SMEMSZ);

    float* bufA = nullptr;
    cudaGetSymbolAddress((void**)&bufA, g_bufA);

    prep_scale<<<Lc, 256>>>(gs);
    prep_wimg<<<(Lc*32768 + Lc*65536 + 65536)/256, 256>>>(W1, W2, Wh1);
    prep_pimg<<<(Lc*65536 + Lc*256)/256, 256>>>(P, go);

    flow_fused<<<NBLK, NTHR, SMEMSZ>>>(feat, bufA, b1, b2, bh1, out);

    stats_kernel<<<1, 256>>>(gamma, beta);
    logits_kernel<<<Bsz/8, 256>>>(bufA, Wh2, bh2, out + Bsz);
}

// round 12
// speedup vs baseline: 1.0109x; 1.0109x over previous
#include <cuda_runtime.h>
#include <cuda_bf16.h>
#include <math.h>
#include <stdint.h>

// ---------------- problem constants ----------------
#define Bsz   131072
#define Dd    256
#define Lc    8
#define NCc   10
#define BN_EPS 1e-5f
#define DGCONST -235.24826450039622f   // D * GCONST

#define MROW  64
#define NTHR  512
#define NBLK  (Bsz/MROW)      // 2048 CTAs

// smem byte offsets (all swizzled images, no padding)
#define XHIo 0
#define XLOo 32768
#define HBo  65536
#define BWo  98304            // 2 x 65536
#define SMEMSZ 229376

// ---------------- static device scratch ----------------
__device__ float g_bufA[(size_t)Bsz*Dd];          // h
__device__ float g_scale[Lc*Dd];
__device__ float g_sumlog[Lc];
__device__ float g_po[Lc*Dd];
__device__ float g_part[(size_t)NBLK*2*Dd];
__device__ float g_stats[2*Dd];
// pre-swizzled bf16 weight images (chunked K=64 smem layout)
__device__ __nv_bfloat16 g_w1t[(size_t)Lc*32768];
__device__ __nv_bfloat16 g_w2t[(size_t)Lc*65536];   // column-PERMUTED (see prep)
__device__ __nv_bfloat16 g_ph [(size_t)Lc*65536];   // P' = P*diag(scale), hi
__device__ __nv_bfloat16 g_pl [(size_t)Lc*65536];
__device__ __nv_bfloat16 g_whh[65536];
__device__ __nv_bfloat16 g_whl[65536];

// ---------------- helpers ----------------
__device__ __forceinline__ uint32_t packbf2(float a, float b) {
    __nv_bfloat162 t = __floats2bfloat162_rn(a, b);
    return *(uint32_t*)&t;
}
__device__ __forceinline__ float2 unpackbf2(uint32_t w) {
    __nv_bfloat162 t = *(__nv_bfloat162*)&w;
    return __bfloat1622float2(t);
}
__device__ __forceinline__ void split2(float a, float b, uint32_t& hw, uint32_t& lw) {
    __nv_bfloat16 ha = __float2bfloat16(a), hb = __float2bfloat16(b);
    float la = a - __bfloat162float(ha), lb = b - __bfloat162float(hb);
    __nv_bfloat162 h; h.x = ha; h.y = hb;
    hw = *(uint32_t*)&h;
    lw = packbf2(la, lb);
}
__device__ __forceinline__ float fast_tanh_scaled(float a) {
    float e = __expf(-0.2f * a);
    return 1.9f * __fdividef(1.f - e, 1.f + e);
}
__device__ __forceinline__ void cpab(void* dst_smem, const void* src) {
    unsigned s = (unsigned)__cvta_generic_to_shared(dst_smem);
    asm volatile("cp.async.cg.shared.global [%0], [%1], 16;" :: "r"(s), "l"(src));
}
#define CP_COMMIT asm volatile("cp.async.commit_group;")
#define CP_WAIT0  asm volatile("cp.async.wait_group 0;")

#define MMA(cd, a0, a1, a2, a3, b0, b1) \
    asm volatile("mma.sync.aligned.m16n8k16.row.col.f32.bf16.bf16.f32 " \
        "{%0,%1,%2,%3}, {%4,%5,%6,%7}, {%8,%9}, {%0,%1,%2,%3};" \
        : "+f"((cd)[0]), "+f"((cd)[1]), "+f"((cd)[2]), "+f"((cd)[3]) \
        : "r"(a0), "r"(a1), "r"(a2), "r"(a3), "r"(b0), "r"(b1))

#define LDSM4(r0, r1, r2, r3, addr) \
    asm volatile("ldmatrix.sync.aligned.m8n8.x4.shared.b16 {%0,%1,%2,%3}, [%4];" \
        : "=r"(r0), "=r"(r1), "=r"(r2), "=r"(r3) : "r"(addr))

__device__ __forceinline__ void stage32(char* dst, const __nv_bfloat16* src, int tid) {
    const char* s = (const char*)src;
    #pragma unroll
    for (int i = 0; i < 4; i++) cpab(dst + tid*16 + i*8192, s + tid*16 + i*8192);
}
__device__ __forceinline__ int imgoff(int n, int k) {
    return n*64 + (((k >> 3) ^ (n & 7)) << 3) + (k & 7);
}

// ---------------- preprocessing (3 launches, coalesced) ----------------
__global__ void prep_scale(const float* __restrict__ gs) {
    __shared__ float red[256];
    int l = blockIdx.x, d = threadIdx.x;
    float x  = 0.5f * gs[l*Dd + d];
    float sp = (x > 20.f) ? x : log1pf(expf(x));
    float s  = 0.2f * sp;
    g_scale[l*Dd + d] = s;
    red[d] = logf(s);
    __syncthreads();
    #pragma unroll
    for (int o = 128; o; o >>= 1) { if (d < o) red[d] += red[d + o]; __syncthreads(); }
    if (d == 0) g_sumlog[l] = red[0];
}
// W1 + W2 + Wh1 images. Thread = one 8-k octet; n fastest -> coalesced reads.
#define W1T_CNT (Lc*256*16)
#define W2T_CNT (Lc*256*32)
#define WHT_CNT (256*32)
__global__ void prep_wimg(const float* __restrict__ W1, const float* __restrict__ W2,
                          const float* __restrict__ Wh1) {
    int idx = blockIdx.x * 256 + threadIdx.x;
    if (idx < W1T_CNT) {
        int n = idx & 255, ko = ((idx >> 8) & 15) * 8, l = idx >> 12;
        __nv_bfloat16 v[8];
        #pragma unroll
        for (int j = 0; j < 8; j++)
            v[j] = __float2bfloat16(W1[((size_t)l*128 + ko + j)*256 + n]);
        *(uint4*)&g_w1t[(size_t)l*32768 + (ko>>6)*16384 + imgoff(n, ko & 63)] = *(uint4*)v;
    } else if (idx < W1T_CNT + W2T_CNT) {
        int j2 = idx - W1T_CNT;
        int n = j2 & 255, ko = ((j2 >> 8) & 31) * 8, l = j2 >> 13;
        int jr = ((n & 127) >> 4) * 32 + ((n >> 7) << 4) + (n & 15);   // column permutation
        __nv_bfloat16 v[8];
        #pragma unroll
        for (int j = 0; j < 8; j++)
            v[j] = __float2bfloat16(W2[((size_t)l*256 + ko + j)*256 + n]);
        *(uint4*)&g_w2t[(size_t)l*65536 + (ko>>6)*16384 + imgoff(jr, ko & 63)] = *(uint4*)v;
    } else if (idx < W1T_CNT + W2T_CNT + WHT_CNT) {
        int j2 = idx - (W1T_CNT + W2T_CNT);
        int n = j2 & 255, ko = (j2 >> 8) * 8;
        __nv_bfloat16 vh[8], vl[8];
        #pragma unroll
        for (int j = 0; j < 8; j++) {
            float v = Wh1[((size_t)(ko + j))*256 + n];
            vh[j] = __float2bfloat16(v);
            vl[j] = __float2bfloat16(v - __bfloat162float(vh[j]));
        }
        size_t o = (size_t)(ko>>6)*16384 + imgoff(n, ko & 63);
        *(uint4*)&g_whh[o] = *(uint4*)vh;
        *(uint4*)&g_whl[o] = *(uint4*)vl;
    }
}
// P images (k-octet fastest -> both reads and writes coalesced) + po
#define PT_CNT (Lc*256*32)
__global__ void prep_pimg(const float* __restrict__ P, const float* __restrict__ go) {
    int idx = blockIdx.x * 256 + threadIdx.x;
    if (idx < PT_CNT) {
        int ko = (idx & 31) * 8, n = (idx >> 5) & 255, l = idx >> 13;
        __nv_bfloat16 vh[8], vl[8];
        #pragma unroll
        for (int j = 0; j < 8; j++) {
            float v = P[((size_t)l*256 + n)*256 + ko + j] * g_scale[l*Dd + ko + j];
            vh[j] = __float2bfloat16(v);
            vl[j] = __float2bfloat16(v - __bfloat162float(vh[j]));
        }
        size_t o = (size_t)l*65536 + (ko>>6)*16384 + imgoff(n, ko & 63);
        *(uint4*)&g_ph[o] = *(uint4*)vh;
        *(uint4*)&g_pl[o] = *(uint4*)vl;
    } else if (idx < PT_CNT + Lc*256) {
        int j = idx - PT_CNT;
        int l = j >> 8, n = j & 255;
        const float* pr = P + ((size_t)l*256 + n)*256;
        const float* o  = go + l*Dd;
        float acc = 0.f;
        for (int k = 0; k < 256; k++) acc += o[k] * pr[k];
        g_po[l*Dd + n] = acc;
    }
}

// ---------------- mega-fused: flow(8 layers) + log_px + head GEMM ----------------
__global__ void __launch_bounds__(NTHR, 1) flow_fused(
    const float* __restrict__ xin, float* __restrict__ hout,
    const float* __restrict__ b1, const float* __restrict__ b2,
    const float* __restrict__ bh1, float* __restrict__ logpx)
{
    extern __shared__ char smem[];
    const uint32_t su = (uint32_t)__cvta_generic_to_shared(smem);
    const uint32_t XHI = su + XHIo, XLO = su + XLOo, HBu = su + HBo, BWu = su + BWo;
    char* bw = smem + BWo;
    float* HBf = (float*)(smem + HBo);

    const int tid = threadIdx.x, lane = tid & 31, wid = tid >> 5;
    const int warpM = wid >> 3, warpN = wid & 7;
    const int g = lane >> 2, t = lane & 3;
    const int mrow0 = warpM * 32;
    const int n0 = warpN * 32;
    const int laneHi = lane >> 4;
    const int key = lane & 7;
    const int aRowB = (lane & 15) * 512;
    const int nloc = ((lane >> 4) << 3) + (lane & 7);
    const int bRow0 = (n0 + nloc) * 128, bRow1 = (n0 + 16 + nloc) * 128;
    const int bsel = (lane >> 3) & 1;
    const int c_base = n0 + 2*t;

    // prologue: stage layer-0 W1 in full (64KB -> buf0 == wb(layer0))
    stage32(bw,         g_w1t,         tid);
    stage32(bw + 32768, g_w1t + 16384, tid); CP_COMMIT;

    // load + split input x once
    {
        const float4* src = (const float4*)(xin + (size_t)blockIdx.x * MROW * Dd);
        #pragma unroll
        for (int i = tid; i < MROW * Dd / 4; i += NTHR) {
            int r = i >> 6, c = (i & 63) * 4;
            float4 v = src[i];
            uint32_t h0, l0, h1, l1;
            split2(v.x, v.y, h0, l0);
            split2(v.z, v.w, h1, l1);
            int off = r*512 + (((c >> 3) ^ (r & 7)) << 4) + (c & 7)*2;
            *(uint2*)(smem + XHIo + off) = make_uint2(h0, h1);
            *(uint2*)(smem + XLOo + off) = make_uint2(l0, l1);
        }
    }

    float cacc[2][4][4];
    float ldacc = 0.f;

    #pragma unroll 1
    for (int layer = 0; layer < Lc; layer++) {
        const float* bb1 = b1 + layer*Dd;
        const float* bb2 = b2 + layer*Dd;
        const __nv_bfloat16* w2img = g_w2t + (size_t)layer*65536;
        const __nv_bfloat16* phimg = g_ph  + (size_t)layer*65536;
        const __nv_bfloat16* plimg = g_pl  + (size_t)layer*65536;
        const uint32_t wbo = (uint32_t)((layer & 1) * 65536);
        const uint32_t obo = 65536u - wbo;

        // ===== GEMM1: H = relu(x1_hi @ W1 + b1), K=128, whole W1 in wb =====
        #pragma unroll
        for (int nt = 0; nt < 4; nt++) {
            int c = c_base + nt*8;
            float f0 = __ldg(bb1 + c), f1 = __ldg(bb1 + c + 1);
            #pragma unroll
            for (int mt = 0; mt < 2; mt++) {
                cacc[mt][nt][0] = f0; cacc[mt][nt][1] = f1;
                cacc[mt][nt][2] = f0; cacc[mt][nt][3] = f1;
            }
        }
        CP_WAIT0; __syncthreads();                                   // S1
        stage32(bw + obo,         w2img,         tid);
        stage32(bw + obo + 32768, w2img + 16384, tid); CP_COMMIT;
        #pragma unroll
        for (int kk = 0; kk < 8; kk++) {
            int gA = kk*2 + laneHi;
            uint32_t A[2][4], B[2][4];
            #pragma unroll
            for (int mt = 0; mt < 2; mt++)
                LDSM4(A[mt][0], A[mt][1], A[mt][2], A[mt][3],
                      XHI + (uint32_t)((mrow0 + mt*16)*512 + aRowB + ((gA ^ key) << 4)));
            uint32_t bb = BWu + wbo + (uint32_t)((kk >> 2) * 32768);
            uint32_t bsw = (uint32_t)(((((kk & 3)*2) + bsel) ^ key) << 4);
            LDSM4(B[0][0], B[0][1], B[0][2], B[0][3], bb + (uint32_t)bRow0 + bsw);
            LDSM4(B[1][0], B[1][1], B[1][2], B[1][3], bb + (uint32_t)bRow1 + bsw);
            #pragma unroll
            for (int p = 0; p < 2; p++)
                #pragma unroll
                for (int q = 0; q < 2; q++) {
                    int nt = p*2 + q;
                    MMA(cacc[0][nt], A[0][0], A[0][1], A[0][2], A[0][3], B[p][q*2], B[p][q*2+1]);
                    MMA(cacc[1][nt], A[1][0], A[1][1], A[1][2], A[1][3], B[p][q*2], B[p][q*2+1]);
                }
        }
        // relu -> HB (unpermuted)
        #pragma unroll
        for (int nt = 0; nt < 4; nt++) {
            int c = c_base + nt*8;
            int csw = ((c >> 3) ^ g) << 4;
            #pragma unroll
            for (int mt = 0; mt < 2; mt++) {
                int r = mrow0 + mt*16 + g;
                float* cf = cacc[mt][nt];
                *(uint32_t*)(smem + HBo + r*512     + csw + 4*t) =
                    packbf2(fmaxf(cf[0], 0.f), fmaxf(cf[1], 0.f));
                *(uint32_t*)(smem + HBo + (r+8)*512 + csw + 4*t) =
                    packbf2(fmaxf(cf[2], 0.f), fmaxf(cf[3], 0.f));
            }
        }

        // ===== GEMM2: A2 = H @ W2perm + b2, K=256 (output cols permuted) =====
        #pragma unroll
        for (int nt = 0; nt < 4; nt++) {
            int p = nt >> 1, q = nt & 1;
            int c2 = p*128 + warpN*16 + q*8 + 2*t;
            float f0 = __ldg(bb2 + c2), f1 = __ldg(bb2 + c2 + 1);
            #pragma unroll
            for (int mt = 0; mt < 2; mt++) {
                cacc[mt][nt][0] = f0; cacc[mt][nt][1] = f1;
                cacc[mt][nt][2] = f0; cacc[mt][nt][3] = f1;
            }
        }
        #pragma unroll 1
        for (int half2 = 0; half2 < 2; half2++) {
            CP_WAIT0; __syncthreads();                               // S2 / S3
            if (half2 == 0) {
                stage32(bw + wbo,         w2img + 32768, tid);
                stage32(bw + wbo + 32768, w2img + 49152, tid); CP_COMMIT;
            } else {
                stage32(bw + obo,         phimg, tid);
                stage32(bw + obo + 32768, plimg, tid); CP_COMMIT;
            }
            uint32_t cur = BWu + ((half2 == 0) ? obo : wbo);
            #pragma unroll
            for (int kk = 0; kk < 8; kk++) {
                int gA = half2*16 + kk*2 + laneHi;
                uint32_t A[2][4], B[2][4];
                #pragma unroll
                for (int mt = 0; mt < 2; mt++)
                    LDSM4(A[mt][0], A[mt][1], A[mt][2], A[mt][3],
                          HBu + (uint32_t)((mrow0 + mt*16)*512 + aRowB + ((gA ^ key) << 4)));
                uint32_t bb = cur + (uint32_t)((kk >> 2) * 32768);
                uint32_t bsw = (uint32_t)(((((kk & 3)*2) + bsel) ^ key) << 4);
                LDSM4(B[0][0], B[0][1], B[0][2], B[0][3], bb + (uint32_t)bRow0 + bsw);
                LDSM4(B[1][0], B[1][1], B[1][2], B[1][3], bb + (uint32_t)bRow1 + bsw);
                #pragma unroll
                for (int p = 0; p < 2; p++)
                    #pragma unroll
                    for (int q = 0; q < 2; q++) {
                        int nt = p*2 + q;
                        MMA(cacc[0][nt], A[0][0], A[0][1], A[0][2], A[0][3], B[p][q*2], B[p][q*2+1]);
                        MMA(cacc[1][nt], A[1][0], A[1][1], A[1][2], A[1][3], B[p][q*2], B[p][q*2+1]);
                    }
            }
        }
        CP_WAIT0; __syncthreads();                                   // S4
        stage32(bw + wbo,         phimg + 16384, tid);
        stage32(bw + wbo + 32768, plimg + 16384, tid); CP_COMMIT;

        // ===== coupling epilogue (register-local; logdet partials in registers) =====
        {
            float lds[2][2] = {{0.f, 0.f}, {0.f, 0.f}};
            #pragma unroll
            for (int q = 0; q < 2; q++) {
                int cs = warpN*16 + q*8 + 2*t;
                int cx = 128 + cs;
                #pragma unroll
                for (int mt = 0; mt < 2; mt++) {
                    #pragma unroll
                    for (int half = 0; half < 2; half++) {
                        int i0 = half*2, r = mrow0 + mt*16 + g + half*8;
                        float s0 = fast_tanh_scaled(cacc[mt][q][i0]);
                        float s1 = fast_tanh_scaled(cacc[mt][q][i0 + 1]);
                        lds[mt][half] += s0 + s1;
                        float a20 = 0.1f * cacc[mt][2 + q][i0];
                        float a21 = 0.1f * cacc[mt][2 + q][i0 + 1];
                        int xo = r*512 + (((cx >> 3) ^ g) << 4) + 4*t;
                        float2 hv = unpackbf2(*(uint32_t*)(smem + XHIo + xo));
                        float2 lv = unpackbf2(*(uint32_t*)(smem + XLOo + xo));
                        float v0 = (hv.x + lv.x) * __expf(s0) + a20;
                        float v1 = (hv.y + lv.y) * __expf(s1) + a21;
                        uint32_t hw, lw; split2(v0, v1, hw, lw);
                        *(uint32_t*)(smem + XHIo + xo) = hw;
                        *(uint32_t*)(smem + XLOo + xo) = lw;
                    }
                }
            }
            // reduce over t (quad) and stage per-(row, warpN) partials
            #pragma unroll
            for (int mt = 0; mt < 2; mt++)
                #pragma unroll
                for (int half = 0; half < 2; half++) {
                    float v = lds[mt][half];
                    v += __shfl_xor_sync(0xffffffffu, v, 1);
                    v += __shfl_xor_sync(0xffffffffu, v, 2);
                    if (t == 0) {
                        int r = mrow0 + mt*16 + g + half*8;
                        HBf[r*8 + warpN] = v;
                    }
                }
        }

        // ===== GEMM3: Xnew = Xc @ P'^T + po, 3-term split, K=256 =====
        {
            const float* po = g_po + layer*Dd;
            #pragma unroll
            for (int nt = 0; nt < 4; nt++) {
                int c = c_base + nt*8;
                float f0 = __ldg(po + c), f1 = __ldg(po + c + 1);
                #pragma unroll
                for (int mt = 0; mt < 2; mt++) {
                    cacc[mt][nt][0] = f0; cacc[mt][nt][1] = f1;
                    cacc[mt][nt][2] = f0; cacc[mt][nt][3] = f1;
                }
            }
            #pragma unroll 1
            for (int ch = 0; ch < 4; ch++) {
                if (ch > 0) {
                    CP_WAIT0; __syncthreads();                       // S6..S8
                    if (ch < 3) {
                        uint32_t dsto = (ch == 1) ? obo : wbo;
                        stage32(bw + dsto,         phimg + (ch+1)*16384, tid);
                        stage32(bw + dsto + 32768, plimg + (ch+1)*16384, tid); CP_COMMIT;
                    } else if (layer + 1 < Lc) {
                        const __nv_bfloat16* w1n = g_w1t + (size_t)(layer+1)*32768;
                        stage32(bw + obo,         w1n,         tid);
                        stage32(bw + obo + 32768, w1n + 16384, tid); CP_COMMIT;
                    } else {
                        stage32(bw + obo,         g_whh, tid);
                        stage32(bw + obo + 32768, g_whl, tid); CP_COMMIT;
                    }
                }
                uint32_t cur = BWu + ((ch & 1) ? wbo : obo);
                #pragma unroll
                for (int ks = 0; ks < 64; ks += 16) {
                    int gA = (ch << 3) + (ks >> 3) + laneHi;
                    uint32_t Ah[2][4], Al[2][4], Bh[2][4], Bl[2][4];
                    #pragma unroll
                    for (int mt = 0; mt < 2; mt++) {
                        uint32_t abase = (uint32_t)((mrow0 + mt*16)*512 + aRowB + ((gA ^ key) << 4));
                        LDSM4(Ah[mt][0], Ah[mt][1], Ah[mt][2], Ah[mt][3], XHI + abase);
                        LDSM4(Al[mt][0], Al[mt][1], Al[mt][2], Al[mt][3], XLO + abase);
                    }
                    uint32_t bsw = (uint32_t)(((((ks >> 3) + bsel) ^ key) << 4));
                    LDSM4(Bh[0][0], Bh[0][1], Bh[0][2], Bh[0][3], cur + (uint32_t)bRow0 + bsw);
                    LDSM4(Bh[1][0], Bh[1][1], Bh[1][2], Bh[1][3], cur + (uint32_t)bRow1 + bsw);
                    LDSM4(Bl[0][0], Bl[0][1], Bl[0][2], Bl[0][3], cur + 32768u + (uint32_t)bRow0 + bsw);
                    LDSM4(Bl[1][0], Bl[1][1], Bl[1][2], Bl[1][3], cur + 32768u + (uint32_t)bRow1 + bsw);
                    #pragma unroll
                    for (int p = 0; p < 2; p++)
                        #pragma unroll
                        for (int q = 0; q < 2; q++) {
                            int nt = p*2 + q;
                            #pragma unroll
                            for (int mt = 0; mt < 2; mt++) {
                                MMA(cacc[mt][nt], Ah[mt][0], Ah[mt][1], Ah[mt][2], Ah[mt][3], Bh[p][q*2], Bh[p][q*2+1]);
                                MMA(cacc[mt][nt], Al[mt][0], Al[mt][1], Al[mt][2], Al[mt][3], Bh[p][q*2], Bh[p][q*2+1]);
                                MMA(cacc[mt][nt], Ah[mt][0], Ah[mt][1], Ah[mt][2], Ah[mt][3], Bl[p][q*2], Bl[p][q*2+1]);
                            }
                        }
                }
            }
            __syncthreads();                                         // S9: X reads + HBf writes fenced
        }

        // logdet from register-staged partials
        if (tid < MROW) {
            float rs = 0.f;
            #pragma unroll
            for (int w = 0; w < 8; w++) rs += HBf[tid*8 + w];
            ldacc += rs + g_sumlog[layer];
        }

        // split accumulators back into XHI/XLO (all layers; final = z)
        #pragma unroll
        for (int nt = 0; nt < 4; nt++) {
            int c = c_base + nt*8;
            int csw = ((c >> 3) ^ g) << 4;
            #pragma unroll
            for (int mt = 0; mt < 2; mt++) {
                float* cf = cacc[mt][nt];
                #pragma unroll
                for (int half = 0; half < 2; half++) {
                    int r = mrow0 + mt*16 + g + half*8;
                    uint32_t hw, lw;
                    split2(cf[half*2 + 0], cf[half*2 + 1], hw, lw);
                    *(uint32_t*)(smem + XHIo + r*512 + csw + 4*t) = hw;
                    *(uint32_t*)(smem + XLOo + r*512 + csw + 4*t) = lw;
                }
            }
        }
    }

    // ===================== fused tail: log_px + head GEMM =====================
    {
        float z2[2][2];
        #pragma unroll
        for (int mt = 0; mt < 2; mt++)
            #pragma unroll
            for (int half = 0; half < 2; half++) {
                float s = 0.f;
                #pragma unroll
                for (int nt = 0; nt < 4; nt++) {
                    float a = cacc[mt][nt][half*2 + 0], b = cacc[mt][nt][half*2 + 1];
                    s += a*a + b*b;
                }
                s += __shfl_xor_sync(0xffffffffu, s, 1);
                s += __shfl_xor_sync(0xffffffffu, s, 2);
                z2[mt][half] = s;
            }
        CP_WAIT0;                      // head wh chunk0 arrived
        __syncthreads();               // S10: logdet reads done
        if (t == 0) {
            #pragma unroll
            for (int mt = 0; mt < 2; mt++)
                #pragma unroll
                for (int half = 0; half < 2; half++) {
                    int r = mrow0 + mt*16 + g + half*8;
                    HBf[r*8 + warpN] = z2[mt][half];
                }
        }
        __syncthreads();               // S11
        if (tid < MROW) {
            float ss = 0.f;
            #pragma unroll
            for (int w = 0; w < 8; w++) ss += HBf[tid*8 + w];
            logpx[(size_t)blockIdx.x * MROW + tid] =
                (DGCONST - 0.5f*ss + ldacc) * (1.0f/Dd);
        }
    }

    // head GEMM: h = z @ Wh1 (3-term) + bh1; buffers: ob=0, wb=65536 (layer7 parity)
    {
        const uint32_t wbo = 65536u, obo = 0u;
        stage32(bw + wbo,         g_whh + 16384, tid);
        stage32(bw + wbo + 32768, g_whl + 16384, tid); CP_COMMIT;

        #pragma unroll
        for (int nt = 0; nt < 4; nt++) {
            int c = c_base + nt*8;
            float f0 = __ldg(bh1 + c), f1 = __ldg(bh1 + c + 1);
            #pragma unroll
            for (int mt = 0; mt < 2; mt++) {
                cacc[mt][nt][0] = f0; cacc[mt][nt][1] = f1;
                cacc[mt][nt][2] = f0; cacc[mt][nt][3] = f1;
            }
        }
        #pragma unroll 1
        for (int ch = 0; ch < 4; ch++) {
            if (ch > 0) {
                CP_WAIT0; __syncthreads();
                if (ch < 3) {
                    uint32_t dsto = (ch == 1) ? obo : wbo;
                    stage32(bw + dsto,         g_whh + (ch+1)*16384, tid);
                    stage32(bw + dsto + 32768, g_whl + (ch+1)*16384, tid); CP_COMMIT;
                }
            }
            uint32_t cur = BWu + ((ch & 1) ? wbo : obo);
            #pragma unroll
            for (int ks = 0; ks < 64; ks += 16) {
                int gA = (ch << 3) + (ks >> 3) + laneHi;
                uint32_t Ah[2][4], Al[2][4], Bh[2][4], Bl[2][4];
                #pragma unroll
                for (int mt = 0; mt < 2; mt++) {
                    uint32_t abase = (uint32_t)((mrow0 + mt*16)*512 + aRowB + ((gA ^ key) << 4));
                    LDSM4(Ah[mt][0], Ah[mt][1], Ah[mt][2], Ah[mt][3], XHI + abase);
                    LDSM4(Al[mt][0], Al[mt][1], Al[mt][2], Al[mt][3], XLO + abase);
                }
                uint32_t bsw = (uint32_t)(((((ks >> 3) + bsel) ^ key) << 4));
                LDSM4(Bh[0][0], Bh[0][1], Bh[0][2], Bh[0][3], cur + (uint32_t)bRow0 + bsw);
                LDSM4(Bh[1][0], Bh[1][1], Bh[1][2], Bh[1][3], cur + (uint32_t)bRow1 + bsw);
                LDSM4(Bl[0][0], Bl[0][1], Bl[0][2], Bl[0][3], cur + 32768u + (uint32_t)bRow0 + bsw);
                LDSM4(Bl[1][0], Bl[1][1], Bl[1][2], Bl[1][3], cur + 32768u + (uint32_t)bRow1 + bsw);
                #pragma unroll
                for (int p = 0; p < 2; p++)
                    #pragma unroll
                    for (int q = 0; q < 2; q++) {
                        int nt = p*2 + q;
                        #pragma unroll
                        for (int mt = 0; mt < 2; mt++) {
                            MMA(cacc[mt][nt], Ah[mt][0], Ah[mt][1], Ah[mt][2], Ah[mt][3], Bh[p][q*2], Bh[p][q*2+1]);
                            MMA(cacc[mt][nt], Al[mt][0], Al[mt][1], Al[mt][2], Al[mt][3], Bh[p][q*2], Bh[p][q*2+1]);
                            MMA(cacc[mt][nt], Ah[mt][0], Ah[mt][1], Ah[mt][2], Ah[mt][3], Bl[p][q*2], Bl[p][q*2+1]);
                        }
                    }
            }
        }
        __syncthreads();               // S12: z reads done, smem free

        // h epilogue: gmem write + fp32 overlay for BN partials
        float* stg = (float*)smem;     // [64][264] over XHI/XLO/HB
        #pragma unroll
        for (int mt = 0; mt < 2; mt++)
            #pragma unroll
            for (int half = 0; half < 2; half++) {
                int rl = mrow0 + mt*16 + g + half*8;
                int r  = blockIdx.x * MROW + rl;
                #pragma unroll
                for (int nt = 0; nt < 4; nt++) {
                    int c = c_base + nt*8;
                    float* cf = cacc[mt][nt];
                    float v0 = cf[half*2 + 0];
                    float v1 = cf[half*2 + 1];
                    *(float2*)(hout + (size_t)r*Dd + c) = make_float2(v0, v1);
                    stg[(size_t)rl*264 + c]     = v0;
                    stg[(size_t)rl*264 + c + 1] = v1;
                }
            }
        __syncthreads();               // S13
        if (tid < Dd) {
            float s = 0.f, q = 0.f;
            #pragma unroll 4
            for (int r = 0; r < MROW; r++) {
                float v = stg[(size_t)r*264 + tid];
                s += v; q += v * v;
            }
            g_part[(size_t)blockIdx.x*2*Dd + tid]      = s;
            g_part[(size_t)blockIdx.x*2*Dd + Dd + tid] = q;
        }
    }
}

// ---------------- BN stats fold ----------------
__global__ void stats_kernel(const float* __restrict__ gamma, const float* __restrict__ beta) {
    int c = threadIdx.x;
    float s0=0.f,s1=0.f,s2=0.f,s3=0.f, q0=0.f,q1=0.f,q2=0.f,q3=0.f;
    for (int i = 0; i < NBLK; i += 4) {
        s0 += g_part[(size_t)(i+0)*2*Dd + c];   q0 += g_part[(size_t)(i+0)*2*Dd + Dd + c];
        s1 += g_part[(size_t)(i+1)*2*Dd + c];   q1 += g_part[(size_t)(i+1)*2*Dd + Dd + c];
        s2 += g_part[(size_t)(i+2)*2*Dd + c];   q2 += g_part[(size_t)(i+2)*2*Dd + Dd + c];
        s3 += g_part[(size_t)(i+3)*2*Dd + c];   q3 += g_part[(size_t)(i+3)*2*Dd + Dd + c];
    }
    float s = (s0+s1)+(s2+s3), q = (q0+q1)+(q2+q3);
    float mu  = s * (1.f/Bsz);
    float var = q * (1.f/Bsz) - mu*mu;
    float a = gamma[c] * rsqrtf(var + BN_EPS);
    g_stats[c]      = a;
    g_stats[Dd + c] = beta[c] - mu * a;
}

// ---------------- logits ----------------
__global__ void __launch_bounds__(256) logits_kernel(
    const float* __restrict__ h, const float* __restrict__ Wh2,
    const float* __restrict__ bh2, float* __restrict__ out)
{
    __shared__ float w2s[Dd*NCc];
    __shared__ float As[Dd], Bs[Dd];
    int tid = threadIdx.x;
    for (int i = tid; i < Dd*NCc; i += 256) w2s[i] = Wh2[i];
    if (tid < Dd) { As[tid] = g_stats[tid]; Bs[tid] = g_stats[Dd + tid]; }
    __syncthreads();

    int warp = tid >> 5, lane = tid & 31;
    size_t row = (size_t)blockIdx.x * 8 + warp;
    const float4* hr = (const float4*)(h + row*Dd);
    float4 v0 = hr[lane*2], v1 = hr[lane*2 + 1];
    int k0 = lane * 8;
    float hn[8];
    hn[0] = fmaxf(v0.x*As[k0+0] + Bs[k0+0], 0.f);
    hn[1] = fmaxf(v0.y*As[k0+1] + Bs[k0+1], 0.f);
    hn[2] = fmaxf(v0.z*As[k0+2] + Bs[k0+2], 0.f);
    hn[3] = fmaxf(v0.w*As[k0+3] + Bs[k0+3], 0.f);
    hn[4] = fmaxf(v1.x*As[k0+4] + Bs[k0+4], 0.f);
    hn[5] = fmaxf(v1.y*As[k0+5] + Bs[k0+5], 0.f);
    hn[6] = fmaxf(v1.z*As[k0+6] + Bs[k0+6], 0.f);
    hn[7] = fmaxf(v1.w*As[k0+7] + Bs[k0+7], 0.f);

    float acc[NCc];
    #pragma unroll
    for (int c = 0; c < NCc; c++) acc[c] = 0.f;
    #pragma unroll
    for (int kk = 0; kk < 8; kk++) {
        float x = hn[kk];
        const float* wr = &w2s[(k0+kk)*NCc];
        #pragma unroll
        for (int c = 0; c < NCc; c++) acc[c] += x * wr[c];
    }
    #pragma unroll
    for (int c = 0; c < NCc; c++) {
        #pragma unroll
        for (int o = 16; o; o >>= 1) acc[c] += __shfl_down_sync(0xffffffffu, acc[c], o);
    }
    if (lane == 0) {
        #pragma unroll
        for (int c = 0; c < NCc; c++) out[row*NCc + c] = acc[c] + __ldg(bh2 + c);
    }
}

// ---------------- launch ----------------
extern "C" void kernel_launch(void* const* d_in, const int* in_sizes, int n_in,
                              void* d_out, int out_size)
{
    const float* feat  = (const float*)d_in[0];
    const float* W1    = (const float*)d_in[1];
    const float* b1    = (const float*)d_in[2];
    const float* W2    = (const float*)d_in[3];
    const float* b2    = (const float*)d_in[4];
    const float* gs    = (const float*)d_in[5];
    const float* go    = (const float*)d_in[6];
    const float* P     = (const float*)d_in[7];
    const float* Wh1   = (const float*)d_in[8];
    const float* bh1   = (const float*)d_in[9];
    const float* gamma = (const float*)d_in[10];
    const float* beta  = (const float*)d_in[11];
    const float* Wh2   = (const float*)d_in[12];
    const float* bh2   = (const float*)d_in[13];
    float* out = (float*)d_out;

    cudaFuncSetAttribute(flow_fused, cudaFuncAttributeMaxDynamicSharedMemorySize, SMEMSZ);

    float* bufA = nullptr;
    cudaGetSymbolAddress((void**)&bufA, g_bufA);

    prep_scale<<<Lc, 256>>>(gs);
    prep_wimg<<<(W1T_CNT + W2T_CNT + WHT_CNT + 255)/256, 256>>>(W1, W2, Wh1);
    prep_pimg<<<(PT_CNT + Lc*256 + 255)/256, 256>>>(P, go);

    flow_fused<<<NBLK, NTHR, SMEMSZ>>>(feat, bufA, b1, b2, bh1, out);

    stats_kernel<<<1, 256>>>(gamma, beta);
    logits_kernel<<<Bsz/8, 256>>>(bufA, Wh2, bh2, out + Bsz);
}

// round 13
// speedup vs baseline: 1.0220x; 1.0110x over previous
#include <cuda_runtime.h>
#include <cuda_bf16.h>
#include <math.h>
#include <stdint.h>

// ---------------- problem constants ----------------
#define Bsz   131072
#define Dd    256
#define Lc    8
#define NCc   10
#define BN_EPS 1e-5f
#define DGCONST -235.24826450039622f   // D * GCONST

#define MROW  64
#define NTHR  512
#define NBLK  (Bsz/MROW)      // 2048 CTAs

// smem byte offsets (all swizzled images, no padding)
#define XHIo 0
#define XLOo 32768
#define HBo  65536
#define BWo  98304            // 2 x 65536
#define SMEMSZ 229376

// ---------------- static device scratch ----------------
__device__ float g_bufA[(size_t)Bsz*Dd];          // h
__device__ float g_scale[Lc*Dd];
__device__ float g_sumlog[Lc];
__device__ float g_po[Lc*Dd];
__device__ float g_part[(size_t)NBLK*2*Dd];
__device__ float g_stats[2*Dd];
// pre-swizzled bf16 weight images (chunked K=64 smem layout)
__device__ __nv_bfloat16 g_w1t[(size_t)Lc*32768];
__device__ __nv_bfloat16 g_w2t[(size_t)Lc*65536];   // column-PERMUTED (see prep)
__device__ __nv_bfloat16 g_ph [(size_t)Lc*65536];   // P' = P*diag(scale), hi
__device__ __nv_bfloat16 g_pl [(size_t)Lc*65536];
__device__ __nv_bfloat16 g_whh[65536];
__device__ __nv_bfloat16 g_whl[65536];

// ---------------- helpers ----------------
__device__ __forceinline__ uint32_t packbf2(float a, float b) {
    __nv_bfloat162 t = __floats2bfloat162_rn(a, b);
    return *(uint32_t*)&t;
}
__device__ __forceinline__ float2 unpackbf2(uint32_t w) {
    __nv_bfloat162 t = *(__nv_bfloat162*)&w;
    return __bfloat1622float2(t);
}
// rounding split (used in prep kernels only)
__device__ __forceinline__ void split2(float a, float b, uint32_t& hw, uint32_t& lw) {
    __nv_bfloat16 ha = __float2bfloat16(a), hb = __float2bfloat16(b);
    float la = a - __bfloat162float(ha), lb = b - __bfloat162float(hb);
    __nv_bfloat162 h; h.x = ha; h.y = hb;
    hw = *(uint32_t*)&h;
    lw = packbf2(la, lb);
}
// fast truncating split (PRMT): hi = upper 16 bits, lo = exact residue truncated
__device__ __forceinline__ void split2t(float a, float b, uint32_t& hw, uint32_t& lw) {
    uint32_t ia = __float_as_uint(a), ib = __float_as_uint(b);
    asm("prmt.b32 %0, %1, %2, 0x7632;" : "=r"(hw) : "r"(ia), "r"(ib));
    float ha = __uint_as_float(ia & 0xFFFF0000u);
    float hb = __uint_as_float(ib & 0xFFFF0000u);
    uint32_t il = __float_as_uint(a - ha), jl = __float_as_uint(b - hb);
    asm("prmt.b32 %0, %1, %2, 0x7632;" : "=r"(lw) : "r"(il), "r"(jl));
}
__device__ __forceinline__ float fast_tanh_scaled(float a) {
    float e = __expf(-0.2f * a);
    return 1.9f * __fdividef(1.f - e, 1.f + e);
}
__device__ __forceinline__ void cpab(void* dst_smem, const void* src) {
    unsigned s = (unsigned)__cvta_generic_to_shared(dst_smem);
    asm volatile("cp.async.cg.shared.global [%0], [%1], 16;" :: "r"(s), "l"(src));
}
#define CP_COMMIT asm volatile("cp.async.commit_group;")
#define CP_WAIT0  asm volatile("cp.async.wait_group 0;")

#define MMA(cd, a0, a1, a2, a3, b0, b1) \
    asm volatile("mma.sync.aligned.m16n8k16.row.col.f32.bf16.bf16.f32 " \
        "{%0,%1,%2,%3}, {%4,%5,%6,%7}, {%8,%9}, {%0,%1,%2,%3};" \
        : "+f"((cd)[0]), "+f"((cd)[1]), "+f"((cd)[2]), "+f"((cd)[3]) \
        : "r"(a0), "r"(a1), "r"(a2), "r"(a3), "r"(b0), "r"(b1))

#define LDSM4(r0, r1, r2, r3, addr) \
    asm volatile("ldmatrix.sync.aligned.m8n8.x4.shared.b16 {%0,%1,%2,%3}, [%4];" \
        : "=r"(r0), "=r"(r1), "=r"(r2), "=r"(r3) : "r"(addr))

__device__ __forceinline__ void stage32(char* dst, const __nv_bfloat16* src, int tid) {
    const char* s = (const char*)src;
    #pragma unroll
    for (int i = 0; i < 4; i++) cpab(dst + tid*16 + i*8192, s + tid*16 + i*8192);
}
__device__ __forceinline__ int imgoff(int n, int k) {
    return n*64 + (((k >> 3) ^ (n & 7)) << 3) + (k & 7);
}

// ---------------- preprocessing (3 launches, coalesced) ----------------
__global__ void prep_scale(const float* __restrict__ gs) {
    __shared__ float red[256];
    int l = blockIdx.x, d = threadIdx.x;
    float x  = 0.5f * gs[l*Dd + d];
    float sp = (x > 20.f) ? x : log1pf(expf(x));
    float s  = 0.2f * sp;
    g_scale[l*Dd + d] = s;
    red[d] = logf(s);
    __syncthreads();
    #pragma unroll
    for (int o = 128; o; o >>= 1) { if (d < o) red[d] += red[d + o]; __syncthreads(); }
    if (d == 0) g_sumlog[l] = red[0];
}
#define W1T_CNT (Lc*256*16)
#define W2T_CNT (Lc*256*32)
#define WHT_CNT (256*32)
__global__ void prep_wimg(const float* __restrict__ W1, const float* __restrict__ W2,
                          const float* __restrict__ Wh1) {
    int idx = blockIdx.x * 256 + threadIdx.x;
    if (idx < W1T_CNT) {
        int n = idx & 255, ko = ((idx >> 8) & 15) * 8, l = idx >> 12;
        __nv_bfloat16 v[8];
        #pragma unroll
        for (int j = 0; j < 8; j++)
            v[j] = __float2bfloat16(W1[((size_t)l*128 + ko + j)*256 + n]);
        *(uint4*)&g_w1t[(size_t)l*32768 + (ko>>6)*16384 + imgoff(n, ko & 63)] = *(uint4*)v;
    } else if (idx < W1T_CNT + W2T_CNT) {
        int j2 = idx - W1T_CNT;
        int n = j2 & 255, ko = ((j2 >> 8) & 31) * 8, l = j2 >> 13;
        int jr = ((n & 127) >> 4) * 32 + ((n >> 7) << 4) + (n & 15);
        __nv_bfloat16 v[8];
        #pragma unroll
        for (int j = 0; j < 8; j++)
            v[j] = __float2bfloat16(W2[((size_t)l*256 + ko + j)*256 + n]);
        *(uint4*)&g_w2t[(size_t)l*65536 + (ko>>6)*16384 + imgoff(jr, ko & 63)] = *(uint4*)v;
    } else if (idx < W1T_CNT + W2T_CNT + WHT_CNT) {
        int j2 = idx - (W1T_CNT + W2T_CNT);
        int n = j2 & 255, ko = (j2 >> 8) * 8;
        __nv_bfloat16 vh[8], vl[8];
        #pragma unroll
        for (int j = 0; j < 8; j++) {
            float v = Wh1[((size_t)(ko + j))*256 + n];
            vh[j] = __float2bfloat16(v);
            vl[j] = __float2bfloat16(v - __bfloat162float(vh[j]));
        }
        size_t o = (size_t)(ko>>6)*16384 + imgoff(n, ko & 63);
        *(uint4*)&g_whh[o] = *(uint4*)vh;
        *(uint4*)&g_whl[o] = *(uint4*)vl;
    }
}
#define PT_CNT (Lc*256*32)
__global__ void prep_pimg(const float* __restrict__ P, const float* __restrict__ go) {
    int idx = blockIdx.x * 256 + threadIdx.x;
    if (idx < PT_CNT) {
        int ko = (idx & 31) * 8, n = (idx >> 5) & 255, l = idx >> 13;
        __nv_bfloat16 vh[8], vl[8];
        #pragma unroll
        for (int j = 0; j < 8; j++) {
            float v = P[((size_t)l*256 + n)*256 + ko + j] * g_scale[l*Dd + ko + j];
            vh[j] = __float2bfloat16(v);
            vl[j] = __float2bfloat16(v - __bfloat162float(vh[j]));
        }
        size_t o = (size_t)l*65536 + (ko>>6)*16384 + imgoff(n, ko & 63);
        *(uint4*)&g_ph[o] = *(uint4*)vh;
        *(uint4*)&g_pl[o] = *(uint4*)vl;
    } else if (idx < PT_CNT + Lc*256) {
        int j = idx - PT_CNT;
        int l = j >> 8, n = j & 255;
        const float* pr = P + ((size_t)l*256 + n)*256;
        const float* o  = go + l*Dd;
        float acc = 0.f;
        for (int k = 0; k < 256; k++) acc += o[k] * pr[k];
        g_po[l*Dd + n] = acc;
    }
}

// ---------------- mega-fused: flow(8 layers) + log_px + head GEMM ----------------
__global__ void __launch_bounds__(NTHR, 1) flow_fused(
    const float* __restrict__ xin, float* __restrict__ hout,
    const float* __restrict__ b1, const float* __restrict__ b2,
    const float* __restrict__ bh1, float* __restrict__ logpx)
{
    extern __shared__ char smem[];
    const uint32_t su = (uint32_t)__cvta_generic_to_shared(smem);
    const uint32_t XHI = su + XHIo, XLO = su + XLOo, HBu = su + HBo, BWu = su + BWo;
    char* bw = smem + BWo;
    float* HBf = (float*)(smem + HBo);

    const int tid = threadIdx.x, lane = tid & 31, wid = tid >> 5;
    const int warpM = wid >> 3, warpN = wid & 7;
    const int g = lane >> 2, t = lane & 3;
    const int mrow0 = warpM * 32;
    const int n0 = warpN * 32;
    const int laneHi = lane >> 4;
    const int key = lane & 7;
    const int aRowB = (lane & 15) * 512;
    const int nloc = ((lane >> 4) << 3) + (lane & 7);
    const int bRow0 = (n0 + nloc) * 128, bRow1 = (n0 + 16 + nloc) * 128;
    const int bsel = (lane >> 3) & 1;
    const int c_base = n0 + 2*t;

    // prologue: stage layer-0 W1 in full (64KB -> buf0 == wb(layer0))
    stage32(bw,         g_w1t,         tid);
    stage32(bw + 32768, g_w1t + 16384, tid); CP_COMMIT;

    // load + split input x once
    {
        const float4* src = (const float4*)(xin + (size_t)blockIdx.x * MROW * Dd);
        #pragma unroll
        for (int i = tid; i < MROW * Dd / 4; i += NTHR) {
            int r = i >> 6, c = (i & 63) * 4;
            float4 v = src[i];
            uint32_t h0, l0, h1, l1;
            split2t(v.x, v.y, h0, l0);
            split2t(v.z, v.w, h1, l1);
            int off = r*512 + (((c >> 3) ^ (r & 7)) << 4) + (c & 7)*2;
            *(uint2*)(smem + XHIo + off) = make_uint2(h0, h1);
            *(uint2*)(smem + XLOo + off) = make_uint2(l0, l1);
        }
    }

    float cacc[2][4][4];
    float ldacc = 0.f;

    #pragma unroll 1
    for (int layer = 0; layer < Lc; layer++) {
        const float* bb1 = b1 + layer*Dd;
        const float* bb2 = b2 + layer*Dd;
        const __nv_bfloat16* w2img = g_w2t + (size_t)layer*65536;
        const __nv_bfloat16* phimg = g_ph  + (size_t)layer*65536;
        const __nv_bfloat16* plimg = g_pl  + (size_t)layer*65536;
        const uint32_t wbo = (uint32_t)((layer & 1) * 65536);
        const uint32_t obo = 65536u - wbo;

        // ===== GEMM1: H = relu(x1_hi @ W1 + b1), K=128, whole W1 in wb =====
        #pragma unroll
        for (int nt = 0; nt < 4; nt++) {
            int c = c_base + nt*8;
            float f0 = __ldg(bb1 + c), f1 = __ldg(bb1 + c + 1);
            #pragma unroll
            for (int mt = 0; mt < 2; mt++) {
                cacc[mt][nt][0] = f0; cacc[mt][nt][1] = f1;
                cacc[mt][nt][2] = f0; cacc[mt][nt][3] = f1;
            }
        }
        CP_WAIT0; __syncthreads();                                   // S1
        stage32(bw + obo,         w2img,         tid);
        stage32(bw + obo + 32768, w2img + 16384, tid); CP_COMMIT;
        #pragma unroll
        for (int kk = 0; kk < 8; kk++) {
            int gA = kk*2 + laneHi;
            uint32_t A[2][4], B[2][4];
            #pragma unroll
            for (int mt = 0; mt < 2; mt++)
                LDSM4(A[mt][0], A[mt][1], A[mt][2], A[mt][3],
                      XHI + (uint32_t)((mrow0 + mt*16)*512 + aRowB + ((gA ^ key) << 4)));
            uint32_t bb = BWu + wbo + (uint32_t)((kk >> 2) * 32768);
            uint32_t bsw = (uint32_t)(((((kk & 3)*2) + bsel) ^ key) << 4);
            LDSM4(B[0][0], B[0][1], B[0][2], B[0][3], bb + (uint32_t)bRow0 + bsw);
            LDSM4(B[1][0], B[1][1], B[1][2], B[1][3], bb + (uint32_t)bRow1 + bsw);
            #pragma unroll
            for (int p = 0; p < 2; p++)
                #pragma unroll
                for (int q = 0; q < 2; q++) {
                    int nt = p*2 + q;
                    MMA(cacc[0][nt], A[0][0], A[0][1], A[0][2], A[0][3], B[p][q*2], B[p][q*2+1]);
                    MMA(cacc[1][nt], A[1][0], A[1][1], A[1][2], A[1][3], B[p][q*2], B[p][q*2+1]);
                }
        }
        // relu -> HB (unpermuted)
        #pragma unroll
        for (int nt = 0; nt < 4; nt++) {
            int c = c_base + nt*8;
            int csw = ((c >> 3) ^ g) << 4;
            #pragma unroll
            for (int mt = 0; mt < 2; mt++) {
                int r = mrow0 + mt*16 + g;
                float* cf = cacc[mt][nt];
                *(uint32_t*)(smem + HBo + r*512     + csw + 4*t) =
                    packbf2(fmaxf(cf[0], 0.f), fmaxf(cf[1], 0.f));
                *(uint32_t*)(smem + HBo + (r+8)*512 + csw + 4*t) =
                    packbf2(fmaxf(cf[2], 0.f), fmaxf(cf[3], 0.f));
            }
        }

        // ===== GEMM2: A2 = H @ W2perm + b2, K=256 (output cols permuted) =====
        #pragma unroll
        for (int nt = 0; nt < 4; nt++) {
            int p = nt >> 1, q = nt & 1;
            int c2 = p*128 + warpN*16 + q*8 + 2*t;
            float f0 = __ldg(bb2 + c2), f1 = __ldg(bb2 + c2 + 1);
            #pragma unroll
            for (int mt = 0; mt < 2; mt++) {
                cacc[mt][nt][0] = f0; cacc[mt][nt][1] = f1;
                cacc[mt][nt][2] = f0; cacc[mt][nt][3] = f1;
            }
        }
        #pragma unroll 1
        for (int half2 = 0; half2 < 2; half2++) {
            CP_WAIT0; __syncthreads();                               // S2 / S3
            if (half2 == 0) {
                stage32(bw + wbo,         w2img + 32768, tid);
                stage32(bw + wbo + 32768, w2img + 49152, tid); CP_COMMIT;
            } else {
                stage32(bw + obo,         phimg, tid);
                stage32(bw + obo + 32768, plimg, tid); CP_COMMIT;
            }
            uint32_t cur = BWu + ((half2 == 0) ? obo : wbo);
            #pragma unroll
            for (int kk = 0; kk < 8; kk++) {
                int gA = half2*16 + kk*2 + laneHi;
                uint32_t A[2][4], B[2][4];
                #pragma unroll
                for (int mt = 0; mt < 2; mt++)
                    LDSM4(A[mt][0], A[mt][1], A[mt][2], A[mt][3],
                          HBu + (uint32_t)((mrow0 + mt*16)*512 + aRowB + ((gA ^ key) << 4)));
                uint32_t bb = cur + (uint32_t)((kk >> 2) * 32768);
                uint32_t bsw = (uint32_t)(((((kk & 3)*2) + bsel) ^ key) << 4);
                LDSM4(B[0][0], B[0][1], B[0][2], B[0][3], bb + (uint32_t)bRow0 + bsw);
                LDSM4(B[1][0], B[1][1], B[1][2], B[1][3], bb + (uint32_t)bRow1 + bsw);
                #pragma unroll
                for (int p = 0; p < 2; p++)
                    #pragma unroll
                    for (int q = 0; q < 2; q++) {
                        int nt = p*2 + q;
                        MMA(cacc[0][nt], A[0][0], A[0][1], A[0][2], A[0][3], B[p][q*2], B[p][q*2+1]);
                        MMA(cacc[1][nt], A[1][0], A[1][1], A[1][2], A[1][3], B[p][q*2], B[p][q*2+1]);
                    }
            }
        }

        // ===== coupling epilogue: HOISTED above S4 (overlaps other warps' GEMM2) =====
        // Touches only XHI/XLO cols >=128 (no reader in flight) + registers.
        float lds0, lds1, lds2, lds3;
        {
            float lds[2][2] = {{0.f, 0.f}, {0.f, 0.f}};
            #pragma unroll
            for (int q = 0; q < 2; q++) {
                int cs = warpN*16 + q*8 + 2*t;
                int cx = 128 + cs;
                #pragma unroll
                for (int mt = 0; mt < 2; mt++) {
                    #pragma unroll
                    for (int half = 0; half < 2; half++) {
                        int i0 = half*2, r = mrow0 + mt*16 + g + half*8;
                        float s0 = fast_tanh_scaled(cacc[mt][q][i0]);
                        float s1 = fast_tanh_scaled(cacc[mt][q][i0 + 1]);
                        lds[mt][half] += s0 + s1;
                        float a20 = 0.1f * cacc[mt][2 + q][i0];
                        float a21 = 0.1f * cacc[mt][2 + q][i0 + 1];
                        int xo = r*512 + (((cx >> 3) ^ g) << 4) + 4*t;
                        float2 hv = unpackbf2(*(uint32_t*)(smem + XHIo + xo));
                        float2 lv = unpackbf2(*(uint32_t*)(smem + XLOo + xo));
                        float v0 = (hv.x + lv.x) * __expf(s0) + a20;
                        float v1 = (hv.y + lv.y) * __expf(s1) + a21;
                        uint32_t hw, lw; split2t(v0, v1, hw, lw);
                        *(uint32_t*)(smem + XHIo + xo) = hw;
                        *(uint32_t*)(smem + XLOo + xo) = lw;
                    }
                }
            }
            // quad reduce (register-local)
            #pragma unroll
            for (int mt = 0; mt < 2; mt++)
                #pragma unroll
                for (int half = 0; half < 2; half++) {
                    float v = lds[mt][half];
                    v += __shfl_xor_sync(0xffffffffu, v, 1);
                    v += __shfl_xor_sync(0xffffffffu, v, 2);
                    lds[mt][half] = v;
                }
            lds0 = lds[0][0]; lds1 = lds[0][1]; lds2 = lds[1][0]; lds3 = lds[1][1];
        }

        CP_WAIT0; __syncthreads();                                   // S4: Pc0 ready; HB reads done
        stage32(bw + wbo,         phimg + 16384, tid);
        stage32(bw + wbo + 32768, plimg + 16384, tid); CP_COMMIT;
        // logdet partial store (HBf aliases HB rows 0-3, safe only after S4)
        if (t == 0) {
            HBf[(mrow0 + g)*8 + warpN]      = lds0;
            HBf[(mrow0 + g + 8)*8 + warpN]  = lds1;
            HBf[(mrow0 + 16 + g)*8 + warpN] = lds2;
            HBf[(mrow0 + 24 + g)*8 + warpN] = lds3;
        }

        // ===== GEMM3: Xnew = Xc @ P'^T + po, 3-term split, K=256 =====
        {
            const float* po = g_po + layer*Dd;
            #pragma unroll
            for (int nt = 0; nt < 4; nt++) {
                int c = c_base + nt*8;
                float f0 = __ldg(po + c), f1 = __ldg(po + c + 1);
                #pragma unroll
                for (int mt = 0; mt < 2; mt++) {
                    cacc[mt][nt][0] = f0; cacc[mt][nt][1] = f1;
                    cacc[mt][nt][2] = f0; cacc[mt][nt][3] = f1;
                }
            }
            #pragma unroll 1
            for (int ch = 0; ch < 4; ch++) {
                if (ch > 0) {
                    CP_WAIT0; __syncthreads();                       // S6..S8
                    if (ch < 3) {
                        uint32_t dsto = (ch == 1) ? obo : wbo;
                        stage32(bw + dsto,         phimg + (ch+1)*16384, tid);
                        stage32(bw + dsto + 32768, plimg + (ch+1)*16384, tid); CP_COMMIT;
                    } else if (layer + 1 < Lc) {
                        const __nv_bfloat16* w1n = g_w1t + (size_t)(layer+1)*32768;
                        stage32(bw + obo,         w1n,         tid);
                        stage32(bw + obo + 32768, w1n + 16384, tid); CP_COMMIT;
                    } else {
                        stage32(bw + obo,         g_whh, tid);
                        stage32(bw + obo + 32768, g_whl, tid); CP_COMMIT;
                    }
                }
                uint32_t cur = BWu + ((ch & 1) ? wbo : obo);
                #pragma unroll
                for (int ks = 0; ks < 64; ks += 16) {
                    int gA = (ch << 3) + (ks >> 3) + laneHi;
                    uint32_t Ah[2][4], Al[2][4], Bh[2][4], Bl[2][4];
                    #pragma unroll
                    for (int mt = 0; mt < 2; mt++) {
                        uint32_t abase = (uint32_t)((mrow0 + mt*16)*512 + aRowB + ((gA ^ key) << 4));
                        LDSM4(Ah[mt][0], Ah[mt][1], Ah[mt][2], Ah[mt][3], XHI + abase);
                        LDSM4(Al[mt][0], Al[mt][1], Al[mt][2], Al[mt][3], XLO + abase);
                    }
                    uint32_t bsw = (uint32_t)(((((ks >> 3) + bsel) ^ key) << 4));
                    LDSM4(Bh[0][0], Bh[0][1], Bh[0][2], Bh[0][3], cur + (uint32_t)bRow0 + bsw);
                    LDSM4(Bh[1][0], Bh[1][1], Bh[1][2], Bh[1][3], cur + (uint32_t)bRow1 + bsw);
                    LDSM4(Bl[0][0], Bl[0][1], Bl[0][2], Bl[0][3], cur + 32768u + (uint32_t)bRow0 + bsw);
                    LDSM4(Bl[1][0], Bl[1][1], Bl[1][2], Bl[1][3], cur + 32768u + (uint32_t)bRow1 + bsw);
                    #pragma unroll
                    for (int p = 0; p < 2; p++)
                        #pragma unroll
                        for (int q = 0; q < 2; q++) {
                            int nt = p*2 + q;
                            #pragma unroll
                            for (int mt = 0; mt < 2; mt++) {
                                MMA(cacc[mt][nt], Ah[mt][0], Ah[mt][1], Ah[mt][2], Ah[mt][3], Bh[p][q*2], Bh[p][q*2+1]);
                                MMA(cacc[mt][nt], Al[mt][0], Al[mt][1], Al[mt][2], Al[mt][3], Bh[p][q*2], Bh[p][q*2+1]);
                                MMA(cacc[mt][nt], Ah[mt][0], Ah[mt][1], Ah[mt][2], Ah[mt][3], Bl[p][q*2], Bl[p][q*2+1]);
                            }
                        }
                }
            }
            __syncthreads();                                         // S9: X reads + HBf writes fenced
        }

        // logdet from staged partials
        if (tid < MROW) {
            float rs = 0.f;
            #pragma unroll
            for (int w = 0; w < 8; w++) rs += HBf[tid*8 + w];
            ldacc += rs + g_sumlog[layer];
        }

        // split accumulators back into XHI/XLO (all layers; final = z)
        #pragma unroll
        for (int nt = 0; nt < 4; nt++) {
            int c = c_base + nt*8;
            int csw = ((c >> 3) ^ g) << 4;
            #pragma unroll
            for (int mt = 0; mt < 2; mt++) {
                float* cf = cacc[mt][nt];
                #pragma unroll
                for (int half = 0; half < 2; half++) {
                    int r = mrow0 + mt*16 + g + half*8;
                    uint32_t hw, lw;
                    split2t(cf[half*2 + 0], cf[half*2 + 1], hw, lw);
                    *(uint32_t*)(smem + XHIo + r*512 + csw + 4*t) = hw;
                    *(uint32_t*)(smem + XLOo + r*512 + csw + 4*t) = lw;
                }
            }
        }
    }

    // ===================== fused tail: log_px + head GEMM =====================
    {
        float z2[2][2];
        #pragma unroll
        for (int mt = 0; mt < 2; mt++)
            #pragma unroll
            for (int half = 0; half < 2; half++) {
                float s = 0.f;
                #pragma unroll
                for (int nt = 0; nt < 4; nt++) {
                    float a = cacc[mt][nt][half*2 + 0], b = cacc[mt][nt][half*2 + 1];
                    s += a*a + b*b;
                }
                s += __shfl_xor_sync(0xffffffffu, s, 1);
                s += __shfl_xor_sync(0xffffffffu, s, 2);
                z2[mt][half] = s;
            }
        CP_WAIT0;                      // head wh chunk0 arrived
        __syncthreads();               // S10: logdet reads done
        if (t == 0) {
            #pragma unroll
            for (int mt = 0; mt < 2; mt++)
                #pragma unroll
                for (int half = 0; half < 2; half++) {
                    int r = mrow0 + mt*16 + g + half*8;
                    HBf[r*8 + warpN] = z2[mt][half];
                }
        }
        __syncthreads();               // S11
        if (tid < MROW) {
            float ss = 0.f;
            #pragma unroll
            for (int w = 0; w < 8; w++) ss += HBf[tid*8 + w];
            logpx[(size_t)blockIdx.x * MROW + tid] =
                (DGCONST - 0.5f*ss + ldacc) * (1.0f/Dd);
        }
    }

    // head GEMM: h = z @ Wh1 (3-term) + bh1; buffers: ob=0, wb=65536 (layer7 parity)
    {
        const uint32_t wbo = 65536u, obo = 0u;
        stage32(bw + wbo,         g_whh + 16384, tid);
        stage32(bw + wbo + 32768, g_whl + 16384, tid); CP_COMMIT;

        #pragma unroll
        for (int nt = 0; nt < 4; nt++) {
            int c = c_base + nt*8;
            float f0 = __ldg(bh1 + c), f1 = __ldg(bh1 + c + 1);
            #pragma unroll
            for (int mt = 0; mt < 2; mt++) {
                cacc[mt][nt][0] = f0; cacc[mt][nt][1] = f1;
                cacc[mt][nt][2] = f0; cacc[mt][nt][3] = f1;
            }
        }
        #pragma unroll 1
        for (int ch = 0; ch < 4; ch++) {
            if (ch > 0) {
                CP_WAIT0; __syncthreads();
                if (ch < 3) {
                    uint32_t dsto = (ch == 1) ? obo : wbo;
                    stage32(bw + dsto,         g_whh + (ch+1)*16384, tid);
                    stage32(bw + dsto + 32768, g_whl + (ch+1)*16384, tid); CP_COMMIT;
                }
            }
            uint32_t cur = BWu + ((ch & 1) ? wbo : obo);
            #pragma unroll
            for (int ks = 0; ks < 64; ks += 16) {
                int gA = (ch << 3) + (ks >> 3) + laneHi;
                uint32_t Ah[2][4], Al[2][4], Bh[2][4], Bl[2][4];
                #pragma unroll
                for (int mt = 0; mt < 2; mt++) {
                    uint32_t abase = (uint32_t)((mrow0 + mt*16)*512 + aRowB + ((gA ^ key) << 4));
                    LDSM4(Ah[mt][0], Ah[mt][1], Ah[mt][2], Ah[mt][3], XHI + abase);
                    LDSM4(Al[mt][0], Al[mt][1], Al[mt][2], Al[mt][3], XLO + abase);
                }
                uint32_t bsw = (uint32_t)(((((ks >> 3) + bsel) ^ key) << 4));
                LDSM4(Bh[0][0], Bh[0][1], Bh[0][2], Bh[0][3], cur + (uint32_t)bRow0 + bsw);
                LDSM4(Bh[1][0], Bh[1][1], Bh[1][2], Bh[1][3], cur + (uint32_t)bRow1 + bsw);
                LDSM4(Bl[0][0], Bl[0][1], Bl[0][2], Bl[0][3], cur + 32768u + (uint32_t)bRow0 + bsw);
                LDSM4(Bl[1][0], Bl[1][1], Bl[1][2], Bl[1][3], cur + 32768u + (uint32_t)bRow1 + bsw);
                #pragma unroll
                for (int p = 0; p < 2; p++)
                    #pragma unroll
                    for (int q = 0; q < 2; q++) {
                        int nt = p*2 + q;
                        #pragma unroll
                        for (int mt = 0; mt < 2; mt++) {
                            MMA(cacc[mt][nt], Ah[mt][0], Ah[mt][1], Ah[mt][2], Ah[mt][3], Bh[p][q*2], Bh[p][q*2+1]);
                            MMA(cacc[mt][nt], Al[mt][0], Al[mt][1], Al[mt][2], Al[mt][3], Bh[p][q*2], Bh[p][q*2+1]);
                            MMA(cacc[mt][nt], Ah[mt][0], Ah[mt][1], Ah[mt][2], Ah[mt][3], Bl[p][q*2], Bl[p][q*2+1]);
                        }
                    }
            }
        }
        __syncthreads();               // S12: z reads done, smem free

        float* stg = (float*)smem;     // [64][264] over XHI/XLO/HB
        #pragma unroll
        for (int mt = 0; mt < 2; mt++)
            #pragma unroll
            for (int half = 0; half < 2; half++) {
                int rl = mrow0 + mt*16 + g + half*8;
                int r  = blockIdx.x * MROW + rl;
                #pragma unroll
                for (int nt = 0; nt < 4; nt++) {
                    int c = c_base + nt*8;
                    float* cf = cacc[mt][nt];
                    float v0 = cf[half*2 + 0];
                    float v1 = cf[half*2 + 1];
                    *(float2*)(hout + (size_t)r*Dd + c) = make_float2(v0, v1);
                    stg[(size_t)rl*264 + c]     = v0;
                    stg[(size_t)rl*264 + c + 1] = v1;
                }
            }
        __syncthreads();               // S13
        if (tid < Dd) {
            float s = 0.f, q = 0.f;
            #pragma unroll 4
            for (int r = 0; r < MROW; r++) {
                float v = stg[(size_t)r*264 + tid];
                s += v; q += v * v;
            }
            g_part[(size_t)blockIdx.x*2*Dd + tid]      = s;
            g_part[(size_t)blockIdx.x*2*Dd + Dd + tid] = q;
        }
    }
}

// ---------------- BN stats fold ----------------
__global__ void stats_kernel(const float* __restrict__ gamma, const float* __restrict__ beta) {
    int c = threadIdx.x;
    float s0=0.f,s1=0.f,s2=0.f,s3=0.f, q0=0.f,q1=0.f,q2=0.f,q3=0.f;
    for (int i = 0; i < NBLK; i += 4) {
        s0 += g_part[(size_t)(i+0)*2*Dd + c];   q0 += g_part[(size_t)(i+0)*2*Dd + Dd + c];
        s1 += g_part[(size_t)(i+1)*2*Dd + c];   q1 += g_part[(size_t)(i+1)*2*Dd + Dd + c];
        s2 += g_part[(size_t)(i+2)*2*Dd + c];   q2 += g_part[(size_t)(i+2)*2*Dd + Dd + c];
        s3 += g_part[(size_t)(i+3)*2*Dd + c];   q3 += g_part[(size_t)(i+3)*2*Dd + Dd + c];
    }
    float s = (s0+s1)+(s2+s3), q = (q0+q1)+(q2+q3);
    float mu  = s * (1.f/Bsz);
    float var = q * (1.f/Bsz) - mu*mu;
    float a = gamma[c] * rsqrtf(var + BN_EPS);
    g_stats[c]      = a;
    g_stats[Dd + c] = beta[c] - mu * a;
}

// ---------------- logits ----------------
__global__ void __launch_bounds__(256) logits_kernel(
    const float* __restrict__ h, const float* __restrict__ Wh2,
    const float* __restrict__ bh2, float* __restrict__ out)
{
    __shared__ float w2s[Dd*NCc];
    __shared__ float As[Dd], Bs[Dd];
    int tid = threadIdx.x;
    for (int i = tid; i < Dd*NCc; i += 256) w2s[i] = Wh2[i];
    if (tid < Dd) { As[tid] = g_stats[tid]; Bs[tid] = g_stats[Dd + tid]; }
    __syncthreads();

    int warp = tid >> 5, lane = tid & 31;
    size_t row = (size_t)blockIdx.x * 8 + warp;
    const float4* hr = (const float4*)(h + row*Dd);
    float4 v0 = hr[lane*2], v1 = hr[lane*2 + 1];
    int k0 = lane * 8;
    float hn[8];
    hn[0] = fmaxf(v0.x*As[k0+0] + Bs[k0+0], 0.f);
    hn[1] = fmaxf(v0.y*As[k0+1] + Bs[k0+1], 0.f);
    hn[2] = fmaxf(v0.z*As[k0+2] + Bs[k0+2], 0.f);
    hn[3] = fmaxf(v0.w*As[k0+3] + Bs[k0+3], 0.f);
    hn[4] = fmaxf(v1.x*As[k0+4] + Bs[k0+4], 0.f);
    hn[5] = fmaxf(v1.y*As[k0+5] + Bs[k0+5], 0.f);
    hn[6] = fmaxf(v1.z*As[k0+6] + Bs[k0+6], 0.f);
    hn[7] = fmaxf(v1.w*As[k0+7] + Bs[k0+7], 0.f);

    float acc[NCc];
    #pragma unroll
    for (int c = 0; c < NCc; c++) acc[c] = 0.f;
    #pragma unroll
    for (int kk = 0; kk < 8; kk++) {
        float x = hn[kk];
        const float* wr = &w2s[(k0+kk)*NCc];
        #pragma unroll
        for (int c = 0; c < NCc; c++) acc[c] += x * wr[c];
    }
    #pragma unroll
    for (int c = 0; c < NCc; c++) {
        #pragma unroll
        for (int o = 16; o; o >>= 1) acc[c] += __shfl_down_sync(0xffffffffu, acc[c], o);
    }
    if (lane == 0) {
        #pragma unroll
        for (int c = 0; c < NCc; c++) out[row*NCc + c] = acc[c] + __ldg(bh2 + c);
    }
}

// ---------------- launch ----------------
extern "C" void kernel_launch(void* const* d_in, const int* in_sizes, int n_in,
                              void* d_out, int out_size)
{
    const float* feat  = (const float*)d_in[0];
    const float* W1    = (const float*)d_in[1];
    const float* b1    = (const float*)d_in[2];
    const float* W2    = (const float*)d_in[3];
    const float* b2    = (const float*)d_in[4];
    const float* gs    = (const float*)d_in[5];
    const float* go    = (const float*)d_in[6];
    const float* P     = (const float*)d_in[7];
    const float* Wh1   = (const float*)d_in[8];
    const float* bh1   = (const float*)d_in[9];
    const float* gamma = (const float*)d_in[10];
    const float* beta  = (const float*)d_in[11];
    const float* Wh2   = (const float*)d_in[12];
    const float* bh2   = (const float*)d_in[13];
    float* out = (float*)d_out;

    cudaFuncSetAttribute(flow_fused, cudaFuncAttributeMaxDynamicSharedMemorySize, SMEMSZ);

    float* bufA = nullptr;
    cudaGetSymbolAddress((void**)&bufA, g_bufA);

    prep_scale<<<Lc, 256>>>(gs);
    prep_wimg<<<(W1T_CNT + W2T_CNT + WHT_CNT + 255)/256, 256>>>(W1, W2, Wh1);
    prep_pimg<<<(PT_CNT + Lc*256 + 255)/256, 256>>>(P, go);

    flow_fused<<<NBLK, NTHR, SMEMSZ>>>(feat, bufA, b1, b2, bh1, out);

    stats_kernel<<<1, 256>>>(gamma, beta);
    logits_kernel<<<Bsz/8, 256>>>(bufA, Wh2, bh2, out + Bsz);
}